// round 1
// baseline (speedup 1.0000x reference)
#include <cuda_runtime.h>
#include <cstdint>

// Problem constants
#define TT 512
#define BB 128
#define HH 512
#define LL 6
#define CC 60
#define J3 75          // 3*J input features
#define K0P 80         // padded K for layer 0
#define BH (BB*HH)     // 65536 lanes
#define MM (TT*BB)     // 65536 GEMM rows
#define NN 512
#define EPSBN 1e-5f

// ---------------- scratch (device globals: allocation-free) ----------------
__device__ float g_bufA[(size_t)MM * HH];   // 134 MB ping
__device__ float g_bufB[(size_t)MM * HH];   // 134 MB pong
__device__ float g_weffT[HH * HH];          // effective W^T  [K,N]
__device__ float g_beff[HH];                // effective bias
__device__ float g_scale[HH];
__device__ float g_shift[HH];
__device__ float g_sum[LL * HH];
__device__ float g_sumsq[LL * HH];

// ---------------- small prep kernels ----------------
__global__ void zero_stats_kernel() {
    int i = blockIdx.x * blockDim.x + threadIdx.x;
    if (i < LL * HH) { g_sum[i] = 0.f; g_sumsq[i] = 0.f; }
}

// pad x [M,75] -> g_bufA [M,80] (zeros in cols 75..79)
__global__ void pad_x_kernel(const float* __restrict__ x) {
    int idx = blockIdx.x * blockDim.x + threadIdx.x;  // < MM*K0P
    if (idx >= MM * K0P) return;
    int m = idx / K0P;
    int k = idx - m * K0P;
    g_bufA[idx] = (k < J3) ? x[m * J3 + k] : 0.f;
}

// W0 [H,75] -> g_weffT [80,H] zero-padded; also copy b0 -> beff
__global__ void prep_w0_kernel(const float* __restrict__ W0, const float* __restrict__ b0) {
    int idx = blockIdx.x * blockDim.x + threadIdx.x;  // < K0P*HH
    if (idx < K0P * HH) {
        int i = idx / HH;
        int h = idx - i * HH;
        g_weffT[idx] = (i < J3) ? W0[h * J3 + i] : 0.f;
    }
    if (idx < HH) g_beff[idx] = b0[idx];
}

// per-channel BN affine from accumulated stats
__global__ void scale_shift_kernel(const float* __restrict__ sum,
                                   const float* __restrict__ sumsq,
                                   const float* __restrict__ gamma,
                                   const float* __restrict__ beta) {
    int h = blockIdx.x * blockDim.x + threadIdx.x;
    if (h >= HH) return;
    const float inv = 1.0f / (float)(TT * BB);
    float mean = sum[h] * inv;
    float var  = sumsq[h] * inv - mean * mean;
    float sc   = gamma[h] * rsqrtf(var + EPSBN);
    g_scale[h] = sc;
    g_shift[h] = beta[h] - mean * sc;
}

// WeffT[i,h] = W[h,i] * scale[i]   (W row-major [H,H])
__global__ void fold_w_kernel(const float* __restrict__ W) {
    int idx = blockIdx.x * blockDim.x + threadIdx.x;  // < HH*HH
    if (idx >= HH * HH) return;
    int i = idx >> 9;
    int h = idx & (HH - 1);
    g_weffT[idx] = W[h * HH + i] * g_scale[i];
}

// beff[h] = bh[h] + sum_i W[h,i]*shift[i]   (one block per h)
__global__ void fold_bias_kernel(const float* __restrict__ W, const float* __restrict__ bh) {
    int h = blockIdx.x;
    int tid = threadIdx.x;  // 128
    float acc = 0.f;
    for (int i = tid; i < HH; i += 128)
        acc = fmaf(W[h * HH + i], g_shift[i], acc);
    __shared__ float red[128];
    red[tid] = acc;
    __syncthreads();
    for (int s = 64; s > 0; s >>= 1) {
        if (tid < s) red[tid] += red[tid + s];
        __syncthreads();
    }
    if (tid == 0) g_beff[h] = bh[h] + red[0];
}

// ---------------- SGEMM: C[M,N] = A[M,K] @ Bt[K,N] + bias[N] ----------------
// BM=128, BN=128, BK=16, 256 threads, 8x8 per thread. M=65536, N=512 fixed.
__global__ __launch_bounds__(256) void sgemm_bias_kernel(
    const float* __restrict__ A, const float* __restrict__ Bt,
    const float* __restrict__ bias, float* __restrict__ C, int K) {
    __shared__ float As[16][129];   // [k][m], +1 pad kills store conflicts
    __shared__ float Bs[16][128];   // [k][n]

    const int tid = threadIdx.x;
    const int m0 = blockIdx.y * 128;
    const int n0 = blockIdx.x * 128;
    const int tm = (tid / 16) * 8;
    const int tn = (tid % 16) * 8;

    const int arow = tid / 4;            // 0..63
    const int acol = (tid & 3) * 4;      // 0,4,8,12
    const int brow = tid / 32;           // 0..7
    const int bcol = (tid & 31) * 4;     // 0..124

    float acc[8][8];
#pragma unroll
    for (int i = 0; i < 8; i++)
#pragma unroll
        for (int j = 0; j < 8; j++) acc[i][j] = 0.f;

    for (int k0 = 0; k0 < K; k0 += 16) {
#pragma unroll
        for (int r = 0; r < 2; r++) {
            int m = arow + r * 64;
            float4 v = *(const float4*)(A + (size_t)(m0 + m) * K + k0 + acol);
            As[acol + 0][m] = v.x;
            As[acol + 1][m] = v.y;
            As[acol + 2][m] = v.z;
            As[acol + 3][m] = v.w;
        }
#pragma unroll
        for (int r = 0; r < 2; r++) {
            int kk = brow + r * 8;
            float4 v = *(const float4*)(Bt + (size_t)(k0 + kk) * NN + n0 + bcol);
            *(float4*)&Bs[kk][bcol] = v;
        }
        __syncthreads();
#pragma unroll
        for (int kk = 0; kk < 16; kk++) {
            float ra[8], rb[8];
#pragma unroll
            for (int j = 0; j < 8; j++) ra[j] = As[kk][tm + j];
#pragma unroll
            for (int j = 0; j < 8; j++) rb[j] = Bs[kk][tn + j];
#pragma unroll
            for (int i = 0; i < 8; i++)
#pragma unroll
                for (int j = 0; j < 8; j++)
                    acc[i][j] = fmaf(ra[i], rb[j], acc[i][j]);
        }
        __syncthreads();
    }

    float rbias[8];
#pragma unroll
    for (int j = 0; j < 8; j++) rbias[j] = bias[n0 + tn + j];

#pragma unroll
    for (int i = 0; i < 8; i++) {
        float4 o1, o2;
        o1.x = acc[i][0] + rbias[0]; o1.y = acc[i][1] + rbias[1];
        o1.z = acc[i][2] + rbias[2]; o1.w = acc[i][3] + rbias[3];
        o2.x = acc[i][4] + rbias[4]; o2.y = acc[i][5] + rbias[5];
        o2.z = acc[i][6] + rbias[6]; o2.w = acc[i][7] + rbias[7];
        float* cp = C + (size_t)(m0 + tm + i) * NN + n0 + tn;
        *(float4*)cp = o1;
        *(float4*)(cp + 4) = o2;
    }
}

// ---------------- IndRNN scan + BN stat accumulation ----------------
// one thread per (b,h) lane; sequential over T; 8-deep load prefetch.
template <bool WRITE_ALL>
__global__ __launch_bounds__(256) void scan_kernel(
    const float* __restrict__ y, float* __restrict__ out,
    const float* __restrict__ u, float* __restrict__ gsum,
    float* __restrict__ gsumsq) {
    int idx = blockIdx.x * blockDim.x + threadIdx.x;  // < BH
    int h = idx & (HH - 1);
    float uu = u[h];
    float s = 0.f, sum = 0.f, sq = 0.f;
    const float* p = y + idx;
    float* q = out + idx;
#pragma unroll 1
    for (int t0 = 0; t0 < TT; t0 += 8) {
        float v[8];
#pragma unroll
        for (int j = 0; j < 8; j++) v[j] = p[(size_t)(t0 + j) * BH];
#pragma unroll
        for (int j = 0; j < 8; j++) {
            s = fmaxf(fmaf(uu, s, v[j]), 0.f);
            if (WRITE_ALL) q[(size_t)(t0 + j) * BH] = s;
            sum += s;
            sq = fmaf(s, s, sq);
        }
    }
    if (!WRITE_ALL) q[(size_t)(TT - 1) * BH] = s;
    atomicAdd(&gsum[h], sum);
    atomicAdd(&gsumsq[h], sq);
}

// ---------------- final: out[b,c] = bout[c] + sum_h bn(hl[b,h])*Wout[c,h] ----
__global__ void final_kernel(const float* __restrict__ hl,
                             const float* __restrict__ Wout,
                             const float* __restrict__ bout,
                             float* __restrict__ out) {
    __shared__ float sh[HH];
    int b = blockIdx.x;
    for (int h = threadIdx.x; h < HH; h += blockDim.x)
        sh[h] = fmaf(hl[b * HH + h], g_scale[h], g_shift[h]);
    __syncthreads();
    int c = threadIdx.x;
    if (c < CC) {
        float acc = bout[c];
#pragma unroll 8
        for (int h = 0; h < HH; h++)
            acc = fmaf(sh[h], Wout[c * HH + h], acc);
        out[b * CC + c] = acc;
    }
}

// ---------------- launcher ----------------
extern "C" void kernel_launch(void* const* d_in, const int* in_sizes, int n_in,
                              void* d_out, int out_size) {
    const float* x     = (const float*)d_in[0];
    const float* W0    = (const float*)d_in[1];
    const float* b0    = (const float*)d_in[2];
    const float* Wh    = (const float*)d_in[3];
    const float* bh    = (const float*)d_in[4];
    const float* u     = (const float*)d_in[5];
    const float* gamma = (const float*)d_in[6];
    const float* beta  = (const float*)d_in[7];
    const float* Wout  = (const float*)d_in[8];
    const float* bout  = (const float*)d_in[9];
    float* out = (float*)d_out;

    float *bufA, *bufB, *weffT, *beff, *sum, *sumsq;
    cudaGetSymbolAddress((void**)&bufA, g_bufA);
    cudaGetSymbolAddress((void**)&bufB, g_bufB);
    cudaGetSymbolAddress((void**)&weffT, g_weffT);
    cudaGetSymbolAddress((void**)&beff, g_beff);
    cudaGetSymbolAddress((void**)&sum, g_sum);
    cudaGetSymbolAddress((void**)&sumsq, g_sumsq);

    zero_stats_kernel<<<(LL * HH + 255) / 256, 256>>>();
    pad_x_kernel<<<(MM * K0P + 255) / 256, 256>>>(x);
    prep_w0_kernel<<<(K0P * HH + 255) / 256, 256>>>(W0, b0);

    dim3 ggrid(NN / 128, MM / 128);

    // ---- layer 0 ----
    sgemm_bias_kernel<<<ggrid, 256>>>(bufA, weffT, beff, bufB, K0P);
    scan_kernel<true><<<BH / 256, 256>>>(bufB, bufA, u, sum, sumsq);

    // ---- layers 1..5 ----
    for (int l = 1; l < LL; l++) {
        const float* Wl  = Wh + (size_t)(l - 1) * HH * HH;
        const float* bhl = bh + (size_t)(l - 1) * HH;
        scale_shift_kernel<<<2, 256>>>(sum + (l - 1) * HH, sumsq + (l - 1) * HH,
                                       gamma + (l - 1) * HH, beta + (l - 1) * HH);
        fold_w_kernel<<<(HH * HH + 255) / 256, 256>>>(Wl);
        fold_bias_kernel<<<HH, 128>>>(Wl, bhl);
        sgemm_bias_kernel<<<ggrid, 256>>>(bufA, weffT, beff, bufB, HH);
        if (l < LL - 1)
            scan_kernel<true><<<BH / 256, 256>>>(bufB, bufA, u + l * HH,
                                                 sum + l * HH, sumsq + l * HH);
        else
            scan_kernel<false><<<BH / 256, 256>>>(bufB, bufA, u + l * HH,
                                                  sum + l * HH, sumsq + l * HH);
    }

    // ---- output head: BN(layer5) folded inline ----
    scale_shift_kernel<<<2, 256>>>(sum + (LL - 1) * HH, sumsq + (LL - 1) * HH,
                                   gamma + (LL - 1) * HH, beta + (LL - 1) * HH);
    final_kernel<<<BB, 64>>>(bufA + (size_t)(TT - 1) * BH, Wout, bout, out);
}

// round 2
// speedup vs baseline: 1.0014x; 1.0014x over previous
#include <cuda_runtime.h>
#include <cstdint>

// Problem constants
#define TT 512
#define BB 128
#define HH 512
#define LL 6
#define CC 60
#define J3 75          // 3*J input features
#define K0P 80         // padded K for layer 0
#define BH (BB*HH)     // 65536 lanes
#define MM (TT*BB)     // 65536 GEMM rows
#define NN 512
#define EPSBN 1e-5f

// ---------------- scratch (device globals: allocation-free) ----------------
__device__ float g_bufA[(size_t)MM * HH];   // 134 MB ping
__device__ float g_bufB[(size_t)MM * HH];   // 134 MB pong
__device__ float g_weffT[HH * HH];          // effective W^T  [K,N]
__device__ float g_beff[HH];                // effective bias
__device__ float g_scale[HH];
__device__ float g_shift[HH];
__device__ float g_sum[LL * HH];
__device__ float g_sumsq[LL * HH];

// ---------------- small prep kernels ----------------
__global__ void zero_stats_kernel() {
    int i = blockIdx.x * blockDim.x + threadIdx.x;
    if (i < LL * HH) { g_sum[i] = 0.f; g_sumsq[i] = 0.f; }
}

// pad x [M,75] -> g_bufA [M,80] (zeros in cols 75..79)
__global__ void pad_x_kernel(const float* __restrict__ x) {
    int idx = blockIdx.x * blockDim.x + threadIdx.x;  // < MM*K0P
    if (idx >= MM * K0P) return;
    int m = idx / K0P;
    int k = idx - m * K0P;
    g_bufA[idx] = (k < J3) ? x[m * J3 + k] : 0.f;
}

// W0 [H,75] -> g_weffT [80,H] zero-padded; also copy b0 -> beff
__global__ void prep_w0_kernel(const float* __restrict__ W0, const float* __restrict__ b0) {
    int idx = blockIdx.x * blockDim.x + threadIdx.x;  // < K0P*HH
    if (idx < K0P * HH) {
        int i = idx / HH;
        int h = idx - i * HH;
        g_weffT[idx] = (i < J3) ? W0[h * J3 + i] : 0.f;
    }
    if (idx < HH) g_beff[idx] = b0[idx];
}

// per-channel BN affine from accumulated stats
__global__ void scale_shift_kernel(const float* __restrict__ sum,
                                   const float* __restrict__ sumsq,
                                   const float* __restrict__ gamma,
                                   const float* __restrict__ beta) {
    int h = blockIdx.x * blockDim.x + threadIdx.x;
    if (h >= HH) return;
    const float inv = 1.0f / (float)(TT * BB);
    float mean = sum[h] * inv;
    float var  = sumsq[h] * inv - mean * mean;
    float sc   = gamma[h] * rsqrtf(var + EPSBN);
    g_scale[h] = sc;
    g_shift[h] = beta[h] - mean * sc;
}

// WeffT[i,h] = W[h,i] * scale[i]   (W row-major [H,H])
__global__ void fold_w_kernel(const float* __restrict__ W) {
    int idx = blockIdx.x * blockDim.x + threadIdx.x;  // < HH*HH
    if (idx >= HH * HH) return;
    int i = idx >> 9;
    int h = idx & (HH - 1);
    g_weffT[idx] = W[h * HH + i] * g_scale[i];
}

// beff[h] = bh[h] + sum_i W[h,i]*shift[i]   (one block per h)
__global__ void fold_bias_kernel(const float* __restrict__ W, const float* __restrict__ bh) {
    int h = blockIdx.x;
    int tid = threadIdx.x;  // 128
    float acc = 0.f;
    for (int i = tid; i < HH; i += 128)
        acc = fmaf(W[h * HH + i], g_shift[i], acc);
    __shared__ float red[128];
    red[tid] = acc;
    __syncthreads();
    for (int s = 64; s > 0; s >>= 1) {
        if (tid < s) red[tid] += red[tid + s];
        __syncthreads();
    }
    if (tid == 0) g_beff[h] = bh[h] + red[0];
}

// ---------------- SGEMM: C[M,N] = A[M,K] @ Bt[K,N] + bias[N] ----------------
// BM=128, BN=128, BK=16, 256 threads, 8x8 per thread. M=65536, N=512 fixed.
__global__ __launch_bounds__(256) void sgemm_bias_kernel(
    const float* __restrict__ A, const float* __restrict__ Bt,
    const float* __restrict__ bias, float* __restrict__ C, int K) {
    __shared__ float As[16][129];   // [k][m], +1 pad kills store conflicts
    __shared__ float Bs[16][128];   // [k][n]

    const int tid = threadIdx.x;
    const int m0 = blockIdx.y * 128;
    const int n0 = blockIdx.x * 128;
    const int tm = (tid / 16) * 8;
    const int tn = (tid % 16) * 8;

    const int arow = tid / 4;            // 0..63
    const int acol = (tid & 3) * 4;      // 0,4,8,12
    const int brow = tid / 32;           // 0..7
    const int bcol = (tid & 31) * 4;     // 0..124

    float acc[8][8];
#pragma unroll
    for (int i = 0; i < 8; i++)
#pragma unroll
        for (int j = 0; j < 8; j++) acc[i][j] = 0.f;

    for (int k0 = 0; k0 < K; k0 += 16) {
#pragma unroll
        for (int r = 0; r < 2; r++) {
            int m = arow + r * 64;
            float4 v = *(const float4*)(A + (size_t)(m0 + m) * K + k0 + acol);
            As[acol + 0][m] = v.x;
            As[acol + 1][m] = v.y;
            As[acol + 2][m] = v.z;
            As[acol + 3][m] = v.w;
        }
#pragma unroll
        for (int r = 0; r < 2; r++) {
            int kk = brow + r * 8;
            float4 v = *(const float4*)(Bt + (size_t)(k0 + kk) * NN + n0 + bcol);
            *(float4*)&Bs[kk][bcol] = v;
        }
        __syncthreads();
#pragma unroll
        for (int kk = 0; kk < 16; kk++) {
            float ra[8], rb[8];
#pragma unroll
            for (int j = 0; j < 8; j++) ra[j] = As[kk][tm + j];
#pragma unroll
            for (int j = 0; j < 8; j++) rb[j] = Bs[kk][tn + j];
#pragma unroll
            for (int i = 0; i < 8; i++)
#pragma unroll
                for (int j = 0; j < 8; j++)
                    acc[i][j] = fmaf(ra[i], rb[j], acc[i][j]);
        }
        __syncthreads();
    }

    float rbias[8];
#pragma unroll
    for (int j = 0; j < 8; j++) rbias[j] = bias[n0 + tn + j];

#pragma unroll
    for (int i = 0; i < 8; i++) {
        float4 o1, o2;
        o1.x = acc[i][0] + rbias[0]; o1.y = acc[i][1] + rbias[1];
        o1.z = acc[i][2] + rbias[2]; o1.w = acc[i][3] + rbias[3];
        o2.x = acc[i][4] + rbias[4]; o2.y = acc[i][5] + rbias[5];
        o2.z = acc[i][6] + rbias[6]; o2.w = acc[i][7] + rbias[7];
        float* cp = C + (size_t)(m0 + tm + i) * NN + n0 + tn;
        *(float4*)cp = o1;
        *(float4*)(cp + 4) = o2;
    }
}

// ---------------- IndRNN scan + BN stat accumulation ----------------
// one thread per (b,h) lane; sequential over T; 8-deep load prefetch.
template <bool WRITE_ALL>
__global__ __launch_bounds__(256) void scan_kernel(
    const float* __restrict__ y, float* __restrict__ out,
    const float* __restrict__ u, float* __restrict__ gsum,
    float* __restrict__ gsumsq) {
    int idx = blockIdx.x * blockDim.x + threadIdx.x;  // < BH
    int h = idx & (HH - 1);
    float uu = u[h];
    float s = 0.f, sum = 0.f, sq = 0.f;
    const float* p = y + idx;
    float* q = out + idx;
#pragma unroll 1
    for (int t0 = 0; t0 < TT; t0 += 8) {
        float v[8];
#pragma unroll
        for (int j = 0; j < 8; j++) v[j] = p[(size_t)(t0 + j) * BH];
#pragma unroll
        for (int j = 0; j < 8; j++) {
            s = fmaxf(fmaf(uu, s, v[j]), 0.f);
            if (WRITE_ALL) q[(size_t)(t0 + j) * BH] = s;
            sum += s;
            sq = fmaf(s, s, sq);
        }
    }
    if (!WRITE_ALL) q[(size_t)(TT - 1) * BH] = s;
    atomicAdd(&gsum[h], sum);
    atomicAdd(&gsumsq[h], sq);
}

// ---------------- final: out[b,c] = bout[c] + sum_h bn(hl[b,h])*Wout[c,h] ----
__global__ void final_kernel(const float* __restrict__ hl,
                             const float* __restrict__ Wout,
                             const float* __restrict__ bout,
                             float* __restrict__ out) {
    __shared__ float sh[HH];
    int b = blockIdx.x;
    for (int h = threadIdx.x; h < HH; h += blockDim.x)
        sh[h] = fmaf(hl[b * HH + h], g_scale[h], g_shift[h]);
    __syncthreads();
    int c = threadIdx.x;
    if (c < CC) {
        float acc = bout[c];
#pragma unroll 8
        for (int h = 0; h < HH; h++)
            acc = fmaf(sh[h], Wout[c * HH + h], acc);
        out[b * CC + c] = acc;
    }
}

// ---------------- launcher ----------------
extern "C" void kernel_launch(void* const* d_in, const int* in_sizes, int n_in,
                              void* d_out, int out_size) {
    const float* x     = (const float*)d_in[0];
    const float* W0    = (const float*)d_in[1];
    const float* b0    = (const float*)d_in[2];
    const float* Wh    = (const float*)d_in[3];
    const float* bh    = (const float*)d_in[4];
    const float* u     = (const float*)d_in[5];
    const float* gamma = (const float*)d_in[6];
    const float* beta  = (const float*)d_in[7];
    const float* Wout  = (const float*)d_in[8];
    const float* bout  = (const float*)d_in[9];
    float* out = (float*)d_out;

    float *bufA, *bufB, *weffT, *beff, *sum, *sumsq;
    cudaGetSymbolAddress((void**)&bufA, g_bufA);
    cudaGetSymbolAddress((void**)&bufB, g_bufB);
    cudaGetSymbolAddress((void**)&weffT, g_weffT);
    cudaGetSymbolAddress((void**)&beff, g_beff);
    cudaGetSymbolAddress((void**)&sum, g_sum);
    cudaGetSymbolAddress((void**)&sumsq, g_sumsq);

    zero_stats_kernel<<<(LL * HH + 255) / 256, 256>>>();
    pad_x_kernel<<<(MM * K0P + 255) / 256, 256>>>(x);
    prep_w0_kernel<<<(K0P * HH + 255) / 256, 256>>>(W0, b0);

    dim3 ggrid(NN / 128, MM / 128);

    // ---- layer 0 ----
    sgemm_bias_kernel<<<ggrid, 256>>>(bufA, weffT, beff, bufB, K0P);
    scan_kernel<true><<<BH / 256, 256>>>(bufB, bufA, u, sum, sumsq);

    // ---- layers 1..5 ----
    for (int l = 1; l < LL; l++) {
        const float* Wl  = Wh + (size_t)(l - 1) * HH * HH;
        const float* bhl = bh + (size_t)(l - 1) * HH;
        scale_shift_kernel<<<2, 256>>>(sum + (l - 1) * HH, sumsq + (l - 1) * HH,
                                       gamma + (l - 1) * HH, beta + (l - 1) * HH);
        fold_w_kernel<<<(HH * HH + 255) / 256, 256>>>(Wl);
        fold_bias_kernel<<<HH, 128>>>(Wl, bhl);
        sgemm_bias_kernel<<<ggrid, 256>>>(bufA, weffT, beff, bufB, HH);
        if (l < LL - 1)
            scan_kernel<true><<<BH / 256, 256>>>(bufB, bufA, u + l * HH,
                                                 sum + l * HH, sumsq + l * HH);
        else
            scan_kernel<false><<<BH / 256, 256>>>(bufB, bufA, u + l * HH,
                                                  sum + l * HH, sumsq + l * HH);
    }

    // ---- output head: BN(layer5) folded inline ----
    scale_shift_kernel<<<2, 256>>>(sum + (LL - 1) * HH, sumsq + (LL - 1) * HH,
                                   gamma + (LL - 1) * HH, beta + (LL - 1) * HH);
    final_kernel<<<BB, 64>>>(bufA + (size_t)(TT - 1) * BH, Wout, bout, out);
}

// round 4
// speedup vs baseline: 1.9822x; 1.9795x over previous
#include <cuda_runtime.h>
#include <cuda_bf16.h>
#include <cstdint>

#define TT 512
#define BB 128
#define HH 512
#define LL 6
#define CC 60
#define J3 75
#define K0P 128
#define BH (BB*HH)
#define MM (TT*BB)
#define NN 512
#define EPSBN 1e-5f

// GEMM tiling
#define BM 128
#define BN 128
#define BK 32
#define GT 256
#define STAGE_BYTES 32768      // 4 arrays x 128 rows x 64B
#define OFF_SA1 0
#define OFF_SA2 8192
#define OFF_SB1 16384
#define OFF_SB2 24576
#define GSMEM_TOTAL (2*STAGE_BYTES)

__device__ float         g_Y[(size_t)MM * HH];
__device__ __nv_bfloat16 g_A1[(size_t)MM * HH];
__device__ __nv_bfloat16 g_A2[(size_t)MM * HH];
__device__ __nv_bfloat16 g_B1[HH * HH];
__device__ __nv_bfloat16 g_B2[HH * HH];
__device__ float g_beff[HH];
__device__ float g_scale[HH];
__device__ float g_shift[HH];
__device__ float g_sum[LL * HH];
__device__ float g_sumsq[LL * HH];
__device__ float g_hlast[BH];

__device__ __forceinline__ uint32_t smem_u32(const void* p) {
    uint32_t a;
    asm("{ .reg .u64 t; cvta.to.shared.u64 t, %1; cvt.u32.u64 %0, t; }" : "=r"(a) : "l"(p));
    return a;
}
__device__ __forceinline__ uint32_t swz64(uint32_t off) { return off ^ ((off >> 3) & 0x30); }
__device__ __forceinline__ void cp16(uint32_t dst, const void* src) {
    asm volatile("cp.async.cg.shared.global [%0], [%1], 16;\n" :: "r"(dst), "l"(src));
}
__device__ __forceinline__ void cp_commit() { asm volatile("cp.async.commit_group;\n" ::: "memory"); }
template <int N> __device__ __forceinline__ void cp_wait() {
    asm volatile("cp.async.wait_group %0;\n" :: "n"(N) : "memory");
}
__device__ __forceinline__ void ldm_x4(uint32_t& r0, uint32_t& r1, uint32_t& r2, uint32_t& r3,
                                       uint32_t addr) {
    asm volatile("ldmatrix.sync.aligned.m8n8.x4.shared.b16 {%0,%1,%2,%3}, [%4];"
        : "=r"(r0), "=r"(r1), "=r"(r2), "=r"(r3) : "r"(addr));
}
__device__ __forceinline__ void mma_bf16(float* c, const uint32_t* a, uint32_t b0, uint32_t b1) {
    asm volatile("mma.sync.aligned.m16n8k16.row.col.f32.bf16.bf16.f32 "
        "{%0,%1,%2,%3}, {%4,%5,%6,%7}, {%8,%9}, {%0,%1,%2,%3};"
        : "+f"(c[0]), "+f"(c[1]), "+f"(c[2]), "+f"(c[3])
        : "r"(a[0]), "r"(a[1]), "r"(a[2]), "r"(a[3]), "r"(b0), "r"(b1));
}
__device__ __forceinline__ void bsplit(float v, __nv_bfloat16& h1, __nv_bfloat16& h2) {
    h1 = __float2bfloat16(v);
    h2 = __float2bfloat16(v - __bfloat162float(h1));
}

__global__ void zero_stats_kernel() {
    int i = blockIdx.x * blockDim.x + threadIdx.x;
    if (i < LL * HH) { g_sum[i] = 0.f; g_sumsq[i] = 0.f; }
}

__global__ void pad_x_kernel(const float* __restrict__ x) {
    int idx = blockIdx.x * blockDim.x + threadIdx.x;
    if (idx >= MM * K0P) return;
    int m = idx >> 7, k = idx & 127;
    float v = (k < J3) ? x[m * J3 + k] : 0.f;
    __nv_bfloat16 h1, h2; bsplit(v, h1, h2);
    g_A1[idx] = h1; g_A2[idx] = h2;
}

__global__ void prep_w0_kernel(const float* __restrict__ W0, const float* __restrict__ b0) {
    int idx = blockIdx.x * blockDim.x + threadIdx.x;
    if (idx < HH * K0P) {
        int n = idx >> 7, k = idx & 127;
        float v = (k < J3) ? W0[n * J3 + k] : 0.f;
        __nv_bfloat16 h1, h2; bsplit(v, h1, h2);
        g_B1[idx] = h1; g_B2[idx] = h2;
    }
    if (idx < HH) g_beff[idx] = b0[idx];
}

__global__ void scale_shift_kernel(const float* __restrict__ sum,
                                   const float* __restrict__ sumsq,
                                   const float* __restrict__ gamma,
                                   const float* __restrict__ beta) {
    int h = blockIdx.x * blockDim.x + threadIdx.x;
    if (h >= HH) return;
    const float inv = 1.0f / (float)(TT * BB);
    float mean = sum[h] * inv;
    float var  = sumsq[h] * inv - mean * mean;
    float sc   = gamma[h] * rsqrtf(var + EPSBN);
    g_scale[h] = sc;
    g_shift[h] = beta[h] - mean * sc;
}

__global__ void fold_w_kernel(const float* __restrict__ W) {
    int idx = blockIdx.x * blockDim.x + threadIdx.x;
    if (idx >= HH * HH) return;
    int k = idx & (HH - 1);
    float v = W[idx] * g_scale[k];
    __nv_bfloat16 h1, h2; bsplit(v, h1, h2);
    g_B1[idx] = h1; g_B2[idx] = h2;
}

__global__ void fold_bias_kernel(const float* __restrict__ W, const float* __restrict__ bh) {
    int h = blockIdx.x;
    int tid = threadIdx.x;
    float acc = 0.f;
    for (int i = tid; i < HH; i += 128)
        acc = fmaf(W[h * HH + i], g_shift[i], acc);
    __shared__ float red[128];
    red[tid] = acc;
    __syncthreads();
    for (int s = 64; s > 0; s >>= 1) {
        if (tid < s) red[tid] += red[tid + s];
        __syncthreads();
    }
    if (tid == 0) g_beff[h] = bh[h] + red[0];
}

// C[M, n0:n0+128] = (A1+A2)[M,K] @ (B1+B2)[N,K]^T + bias  (3-pass bf16 split, HMMA)
__global__ __launch_bounds__(GT, 1) void gemm_tc(
    const __nv_bfloat16* __restrict__ A1, const __nv_bfloat16* __restrict__ A2,
    const __nv_bfloat16* __restrict__ B1, const __nv_bfloat16* __restrict__ B2,
    const float* __restrict__ bias, float* __restrict__ C, int K) {
    extern __shared__ __align__(128) char smem[];
    const uint32_t sb = smem_u32(smem);
    const int tid = threadIdx.x, wid = tid >> 5, lane = tid & 31;
    const int n0 = blockIdx.x * BN;
    const int m0 = blockIdx.y * BM;
    const int NC = K / BK;
    const int wm = wid & 3;       // 4 m-warps -> 32 rows each
    const int wn = wid >> 2;      // 2 n-warps -> 64 cols each

    float acc[2][8][4];
#pragma unroll
    for (int i = 0; i < 2; i++)
#pragma unroll
        for (int j = 0; j < 8; j++)
#pragma unroll
            for (int q = 0; q < 4; q++) acc[i][j][q] = 0.f;

    auto load_stage = [&](int c, int s) {
        const uint32_t st = sb + s * STAGE_BYTES;
        const int k0 = c * BK;
#pragma unroll
        for (int i = 0; i < 8; i++) {
            int g = i * GT + tid;            // 0..2047
            int arr = g >> 9;                // 0:A1 1:A2 2:B1 3:B2
            int rem = g & 511;
            int row = rem >> 2, ch = rem & 3;
            const __nv_bfloat16* src;
            if (arr == 0)      src = A1 + ((size_t)(m0 + row) * K + k0 + ch * 8);
            else if (arr == 1) src = A2 + ((size_t)(m0 + row) * K + k0 + ch * 8);
            else if (arr == 2) src = B1 + ((size_t)(n0 + row) * K + k0 + ch * 8);
            else               src = B2 + ((size_t)(n0 + row) * K + k0 + ch * 8);
            cp16(st + arr * 8192 + swz64((uint32_t)(row * 64 + ch * 16)), src);
        }
        cp_commit();
    };

    load_stage(0, 0);

    for (int c = 0; c < NC; c++) {
        const bool more = (c + 1 < NC);
        if (more) load_stage(c + 1, (c + 1) & 1);
        if (more) cp_wait<1>(); else cp_wait<0>();
        __syncthreads();
        const uint32_t st = sb + (c & 1) * STAGE_BYTES;
#pragma unroll
        for (int ks = 0; ks < 2; ks++) {
            const uint32_t cb = ks * 32 + (lane >> 4) * 16;
            uint32_t a1f[2][4], a2f[2][4];
#pragma unroll
            for (int mi = 0; mi < 2; mi++) {
                uint32_t row = wm * 32 + mi * 16 + (lane & 15);
                uint32_t off = swz64(row * 64 + cb);
                ldm_x4(a1f[mi][0], a1f[mi][1], a1f[mi][2], a1f[mi][3], st + OFF_SA1 + off);
                ldm_x4(a2f[mi][0], a2f[mi][1], a2f[mi][2], a2f[mi][3], st + OFF_SA2 + off);
            }
            uint32_t b1f[8][2], b2f[8][2];
#pragma unroll
            for (int ni = 0; ni < 4; ni++) {
                uint32_t row = wn * 64 + ni * 16 + (lane & 15);
                uint32_t off = swz64(row * 64 + cb);
                uint32_t r0, r1, r2, r3;
                ldm_x4(r0, r1, r2, r3, st + OFF_SB1 + off);
                b1f[2*ni][0] = r0; b1f[2*ni][1] = r2;
                b1f[2*ni+1][0] = r1; b1f[2*ni+1][1] = r3;
                ldm_x4(r0, r1, r2, r3, st + OFF_SB2 + off);
                b2f[2*ni][0] = r0; b2f[2*ni][1] = r2;
                b2f[2*ni+1][0] = r1; b2f[2*ni+1][1] = r3;
            }
#pragma unroll
            for (int mi = 0; mi < 2; mi++)
#pragma unroll
                for (int nf = 0; nf < 8; nf++) {
                    mma_bf16(acc[mi][nf], a1f[mi], b1f[nf][0], b1f[nf][1]);
                    mma_bf16(acc[mi][nf], a1f[mi], b2f[nf][0], b2f[nf][1]);
                    mma_bf16(acc[mi][nf], a2f[mi], b1f[nf][0], b1f[nf][1]);
                }
        }
        __syncthreads();
    }

    // epilogue: acc frag layout m16n8: c0,c1 at (lane>>2, (lane&3)*2 +0/1); c2,c3 at row+8
    const int group = lane >> 2, tid4 = lane & 3;
#pragma unroll
    for (int nf = 0; nf < 8; nf++) {
        int nb = n0 + wn * 64 + nf * 8 + tid4 * 2;
        float2 bv = *(const float2*)(bias + nb);
#pragma unroll
        for (int mi = 0; mi < 2; mi++) {
            int mb = m0 + wm * 32 + mi * 16 + group;
            float2 v0 = { acc[mi][nf][0] + bv.x, acc[mi][nf][1] + bv.y };
            float2 v1 = { acc[mi][nf][2] + bv.x, acc[mi][nf][3] + bv.y };
            *(float2*)(C + (size_t)mb * NN + nb) = v0;
            *(float2*)(C + (size_t)(mb + 8) * NN + nb) = v1;
        }
    }
}

// scan: h_t = relu(y_t + u h_{t-1}); writes bf16 split (or last slice)
template <bool WRITE_ALL>
__global__ __launch_bounds__(256) void scan_kernel(
    const float* __restrict__ y, __nv_bfloat16* __restrict__ o1,
    __nv_bfloat16* __restrict__ o2, float* __restrict__ olast,
    const float* __restrict__ u, float* __restrict__ gsum,
    float* __restrict__ gsumsq) {
    int idx = blockIdx.x * blockDim.x + threadIdx.x;
    int h = idx & (HH - 1);
    float uu = u[h];
    float s = 0.f, sum = 0.f, sq = 0.f;
    const float* p = y + idx;
#pragma unroll 1
    for (int t0 = 0; t0 < TT; t0 += 8) {
        float v[8];
#pragma unroll
        for (int j = 0; j < 8; j++) v[j] = p[(size_t)(t0 + j) * BH];
#pragma unroll
        for (int j = 0; j < 8; j++) {
            s = fmaxf(fmaf(uu, s, v[j]), 0.f);
            if (WRITE_ALL) {
                __nv_bfloat16 h1, h2; bsplit(s, h1, h2);
                o1[(size_t)(t0 + j) * BH + idx] = h1;
                o2[(size_t)(t0 + j) * BH + idx] = h2;
            }
            sum += s;
            sq = fmaf(s, s, sq);
        }
    }
    if (!WRITE_ALL) olast[idx] = s;
    atomicAdd(&gsum[h], sum);
    atomicAdd(&gsumsq[h], sq);
}

__global__ void final_kernel(const float* __restrict__ hl,
                             const float* __restrict__ Wout,
                             const float* __restrict__ bout,
                             float* __restrict__ out) {
    __shared__ float sh[HH];
    int b = blockIdx.x;
    for (int h = threadIdx.x; h < HH; h += blockDim.x)
        sh[h] = fmaf(hl[b * HH + h], g_scale[h], g_shift[h]);
    __syncthreads();
    int c = threadIdx.x;
    if (c < CC) {
        float acc = bout[c];
#pragma unroll 8
        for (int h = 0; h < HH; h++)
            acc = fmaf(sh[h], Wout[c * HH + h], acc);
        out[b * CC + c] = acc;
    }
}

extern "C" void kernel_launch(void* const* d_in, const int* in_sizes, int n_in,
                              void* d_out, int out_size) {
    const float* x     = (const float*)d_in[0];
    const float* W0    = (const float*)d_in[1];
    const float* b0    = (const float*)d_in[2];
    const float* Wh    = (const float*)d_in[3];
    const float* bh    = (const float*)d_in[4];
    const float* u     = (const float*)d_in[5];
    const float* gamma = (const float*)d_in[6];
    const float* beta  = (const float*)d_in[7];
    const float* Wout  = (const float*)d_in[8];
    const float* bout  = (const float*)d_in[9];
    float* out = (float*)d_out;

    float *Y, *beff, *sum, *sumsq, *hlast;
    __nv_bfloat16 *A1, *A2, *B1, *B2;
    cudaGetSymbolAddress((void**)&Y, g_Y);
    cudaGetSymbolAddress((void**)&A1, g_A1);
    cudaGetSymbolAddress((void**)&A2, g_A2);
    cudaGetSymbolAddress((void**)&B1, g_B1);
    cudaGetSymbolAddress((void**)&B2, g_B2);
    cudaGetSymbolAddress((void**)&beff, g_beff);
    cudaGetSymbolAddress((void**)&sum, g_sum);
    cudaGetSymbolAddress((void**)&sumsq, g_sumsq);
    cudaGetSymbolAddress((void**)&hlast, g_hlast);

    cudaFuncSetAttribute(gemm_tc, cudaFuncAttributeMaxDynamicSharedMemorySize, GSMEM_TOTAL);

    zero_stats_kernel<<<(LL * HH + 255) / 256, 256>>>();
    pad_x_kernel<<<(MM * K0P + 255) / 256, 256>>>(x);
    prep_w0_kernel<<<(HH * K0P + 255) / 256, 256>>>(W0, b0);

    dim3 ggrid(NN / BN, MM / BM);

    gemm_tc<<<ggrid, GT, GSMEM_TOTAL>>>(A1, A2, B1, B2, beff, Y, K0P);
    scan_kernel<true><<<BH / 256, 256>>>(Y, A1, A2, hlast, u, sum, sumsq);

    for (int l = 1; l < LL; l++) {
        const float* Wl  = Wh + (size_t)(l - 1) * HH * HH;
        const float* bhl = bh + (size_t)(l - 1) * HH;
        scale_shift_kernel<<<2, 256>>>(sum + (l - 1) * HH, sumsq + (l - 1) * HH,
                                       gamma + (l - 1) * HH, beta + (l - 1) * HH);
        fold_w_kernel<<<(HH * HH + 255) / 256, 256>>>(Wl);
        fold_bias_kernel<<<HH, 128>>>(Wl, bhl);
        gemm_tc<<<ggrid, GT, GSMEM_TOTAL>>>(A1, A2, B1, B2, beff, Y, HH);
        if (l < LL - 1)
            scan_kernel<true><<<BH / 256, 256>>>(Y, A1, A2, hlast, u + l * HH,
                                                 sum + l * HH, sumsq + l * HH);
        else
            scan_kernel<false><<<BH / 256, 256>>>(Y, A1, A2, hlast, u + l * HH,
                                                  sum + l * HH, sumsq + l * HH);
    }

    scale_shift_kernel<<<2, 256>>>(sum + (LL - 1) * HH, sumsq + (LL - 1) * HH,
                                   gamma + (LL - 1) * HH, beta + (LL - 1) * HH);
    final_kernel<<<BB, 64>>>(hlast, Wout, bout, out);
}

// round 5
// speedup vs baseline: 2.0368x; 1.0275x over previous
#include <cuda_runtime.h>
#include <cuda_bf16.h>
#include <cstdint>

#define TT 512
#define BB 128
#define HH 512
#define LL 6
#define CC 60
#define J3 75
#define K0P 128
#define BH (BB*HH)
#define MM (TT*BB)
#define NN 512
#define EPSBN 1e-5f

// GEMM tiling: BM=128, BN=128, BK=32, 512 threads (16 warps, 4x4 grid of 32x32 warp tiles)
#define BM 128
#define BN 128
#define BK 32
#define GT 512
#define NSTAGE 4
#define STAGE_BYTES 32768      // 4 arrays x 128 rows x 64B
#define OFF_SA1 0
#define OFF_SA2 8192
#define OFF_SB1 16384
#define OFF_SB2 24576
#define GSMEM_TOTAL (NSTAGE*STAGE_BYTES)

__device__ float         g_Y[(size_t)MM * HH];
__device__ __nv_bfloat16 g_A1[(size_t)MM * HH];
__device__ __nv_bfloat16 g_A2[(size_t)MM * HH];
__device__ __nv_bfloat16 g_B1[HH * HH];
__device__ __nv_bfloat16 g_B2[HH * HH];
__device__ float g_beff[HH];
__device__ float g_scale[HH];
__device__ float g_shift[HH];
__device__ float g_sum[LL * HH];
__device__ float g_sumsq[LL * HH];
__device__ float g_hlast[BH];

__device__ __forceinline__ uint32_t smem_u32(const void* p) {
    uint32_t a;
    asm("{ .reg .u64 t; cvta.to.shared.u64 t, %1; cvt.u32.u64 %0, t; }" : "=r"(a) : "l"(p));
    return a;
}
__device__ __forceinline__ uint32_t swz64(uint32_t off) { return off ^ ((off >> 3) & 0x30); }
__device__ __forceinline__ void cp16(uint32_t dst, const void* src) {
    asm volatile("cp.async.cg.shared.global [%0], [%1], 16;\n" :: "r"(dst), "l"(src));
}
__device__ __forceinline__ void cp_commit() { asm volatile("cp.async.commit_group;\n" ::: "memory"); }
template <int N> __device__ __forceinline__ void cp_wait() {
    asm volatile("cp.async.wait_group %0;\n" :: "n"(N) : "memory");
}
__device__ __forceinline__ void ldm_x4(uint32_t& r0, uint32_t& r1, uint32_t& r2, uint32_t& r3,
                                       uint32_t addr) {
    asm volatile("ldmatrix.sync.aligned.m8n8.x4.shared.b16 {%0,%1,%2,%3}, [%4];"
        : "=r"(r0), "=r"(r1), "=r"(r2), "=r"(r3) : "r"(addr));
}
__device__ __forceinline__ void mma_bf16(float* c, const uint32_t* a, uint32_t b0, uint32_t b1) {
    asm volatile("mma.sync.aligned.m16n8k16.row.col.f32.bf16.bf16.f32 "
        "{%0,%1,%2,%3}, {%4,%5,%6,%7}, {%8,%9}, {%0,%1,%2,%3};"
        : "+f"(c[0]), "+f"(c[1]), "+f"(c[2]), "+f"(c[3])
        : "r"(a[0]), "r"(a[1]), "r"(a[2]), "r"(a[3]), "r"(b0), "r"(b1));
}
__device__ __forceinline__ void bsplit(float v, __nv_bfloat16& h1, __nv_bfloat16& h2) {
    h1 = __float2bfloat16(v);
    h2 = __float2bfloat16(v - __bfloat162float(h1));
}

__global__ void zero_stats_kernel() {
    int i = blockIdx.x * blockDim.x + threadIdx.x;
    if (i < LL * HH) { g_sum[i] = 0.f; g_sumsq[i] = 0.f; }
}

__global__ void pad_x_kernel(const float* __restrict__ x) {
    int idx = blockIdx.x * blockDim.x + threadIdx.x;
    if (idx >= MM * K0P) return;
    int m = idx >> 7, k = idx & 127;
    float v = (k < J3) ? x[m * J3 + k] : 0.f;
    __nv_bfloat16 h1, h2; bsplit(v, h1, h2);
    g_A1[idx] = h1; g_A2[idx] = h2;
}

__global__ void prep_w0_kernel(const float* __restrict__ W0, const float* __restrict__ b0) {
    int idx = blockIdx.x * blockDim.x + threadIdx.x;
    if (idx < HH * K0P) {
        int n = idx >> 7, k = idx & 127;
        float v = (k < J3) ? W0[n * J3 + k] : 0.f;
        __nv_bfloat16 h1, h2; bsplit(v, h1, h2);
        g_B1[idx] = h1; g_B2[idx] = h2;
    }
    if (idx < HH) g_beff[idx] = b0[idx];
}

__global__ void scale_shift_kernel(const float* __restrict__ sum,
                                   const float* __restrict__ sumsq,
                                   const float* __restrict__ gamma,
                                   const float* __restrict__ beta) {
    int h = blockIdx.x * blockDim.x + threadIdx.x;
    if (h >= HH) return;
    const float inv = 1.0f / (float)(TT * BB);
    float mean = sum[h] * inv;
    float var  = sumsq[h] * inv - mean * mean;
    float sc   = gamma[h] * rsqrtf(var + EPSBN);
    g_scale[h] = sc;
    g_shift[h] = beta[h] - mean * sc;
}

__global__ void fold_w_kernel(const float* __restrict__ W) {
    int idx = blockIdx.x * blockDim.x + threadIdx.x;
    if (idx >= HH * HH) return;
    int k = idx & (HH - 1);
    float v = W[idx] * g_scale[k];
    __nv_bfloat16 h1, h2; bsplit(v, h1, h2);
    g_B1[idx] = h1; g_B2[idx] = h2;
}

__global__ void fold_bias_kernel(const float* __restrict__ W, const float* __restrict__ bh) {
    int h = blockIdx.x;
    int tid = threadIdx.x;
    float acc = 0.f;
    for (int i = tid; i < HH; i += 128)
        acc = fmaf(W[h * HH + i], g_shift[i], acc);
    __shared__ float red[128];
    red[tid] = acc;
    __syncthreads();
    for (int s = 64; s > 0; s >>= 1) {
        if (tid < s) red[tid] += red[tid + s];
        __syncthreads();
    }
    if (tid == 0) g_beff[h] = bh[h] + red[0];
}

// C[M, n0:n0+128] = (A1+A2)[M,K] @ (B1+B2)[N,K]^T + bias  (3-pass bf16 split, HMMA)
__global__ __launch_bounds__(GT, 1) void gemm_tc(
    const __nv_bfloat16* __restrict__ A1, const __nv_bfloat16* __restrict__ A2,
    const __nv_bfloat16* __restrict__ B1, const __nv_bfloat16* __restrict__ B2,
    const float* __restrict__ bias, float* __restrict__ C, int K) {
    extern __shared__ __align__(128) char smem[];
    const uint32_t sb = smem_u32(smem);
    const int tid = threadIdx.x, wid = tid >> 5, lane = tid & 31;
    const int n0 = blockIdx.x * BN;
    const int m0 = blockIdx.y * BM;
    const int NC = K / BK;
    const int wm = wid & 3;       // 4 m-warps -> 32 rows each
    const int wn = wid >> 2;      // 4 n-warps -> 32 cols each

    float acc[2][4][4];
#pragma unroll
    for (int i = 0; i < 2; i++)
#pragma unroll
        for (int j = 0; j < 4; j++)
#pragma unroll
            for (int q = 0; q < 4; q++) acc[i][j][q] = 0.f;

    auto load_stage = [&](int c, int s) {
        const uint32_t st = sb + s * STAGE_BYTES;
        const int k0 = c * BK;
#pragma unroll
        for (int i = 0; i < 4; i++) {
            int g = i * GT + tid;            // 0..2047
            int arr = g >> 9;                // 0:A1 1:A2 2:B1 3:B2
            int rem = g & 511;
            int row = rem >> 2, ch = rem & 3;
            const __nv_bfloat16* src;
            if (arr == 0)      src = A1 + ((size_t)(m0 + row) * K + k0 + ch * 8);
            else if (arr == 1) src = A2 + ((size_t)(m0 + row) * K + k0 + ch * 8);
            else if (arr == 2) src = B1 + ((size_t)(n0 + row) * K + k0 + ch * 8);
            else               src = B2 + ((size_t)(n0 + row) * K + k0 + ch * 8);
            cp16(st + arr * 8192 + swz64((uint32_t)(row * 64 + ch * 16)), src);
        }
        cp_commit();
    };

    // prologue: fill NSTAGE-1 stages (commit one group per stage)
#pragma unroll
    for (int s = 0; s < NSTAGE - 1; s++) {
        if (s < NC) load_stage(s, s); else cp_commit();
    }

    for (int c = 0; c < NC; c++) {
        cp_wait<NSTAGE - 2>();
        __syncthreads();
        // issue next load (or empty group to keep the count cadence)
        if (c + NSTAGE - 1 < NC) load_stage(c + NSTAGE - 1, (c + NSTAGE - 1) & (NSTAGE - 1));
        else cp_commit();

        const uint32_t st = sb + (c & (NSTAGE - 1)) * STAGE_BYTES;
#pragma unroll
        for (int ks = 0; ks < 2; ks++) {
            const uint32_t cb = ks * 32 + (lane >> 4) * 16;
            uint32_t a1f[2][4], a2f[2][4];
#pragma unroll
            for (int mi = 0; mi < 2; mi++) {
                uint32_t row = wm * 32 + mi * 16 + (lane & 15);
                uint32_t off = swz64(row * 64 + cb);
                ldm_x4(a1f[mi][0], a1f[mi][1], a1f[mi][2], a1f[mi][3], st + OFF_SA1 + off);
                ldm_x4(a2f[mi][0], a2f[mi][1], a2f[mi][2], a2f[mi][3], st + OFF_SA2 + off);
            }
            uint32_t b1f[4][2], b2f[4][2];
#pragma unroll
            for (int ni = 0; ni < 2; ni++) {
                uint32_t row = wn * 32 + ni * 16 + (lane & 15);
                uint32_t off = swz64(row * 64 + cb);
                uint32_t r0, r1, r2, r3;
                ldm_x4(r0, r1, r2, r3, st + OFF_SB1 + off);
                b1f[2*ni][0] = r0; b1f[2*ni][1] = r2;
                b1f[2*ni+1][0] = r1; b1f[2*ni+1][1] = r3;
                ldm_x4(r0, r1, r2, r3, st + OFF_SB2 + off);
                b2f[2*ni][0] = r0; b2f[2*ni][1] = r2;
                b2f[2*ni+1][0] = r1; b2f[2*ni+1][1] = r3;
            }
            // three passes, each a full sweep -> max reuse distance per accumulator
#pragma unroll
            for (int mi = 0; mi < 2; mi++)
#pragma unroll
                for (int nf = 0; nf < 4; nf++)
                    mma_bf16(acc[mi][nf], a1f[mi], b1f[nf][0], b1f[nf][1]);
#pragma unroll
            for (int mi = 0; mi < 2; mi++)
#pragma unroll
                for (int nf = 0; nf < 4; nf++)
                    mma_bf16(acc[mi][nf], a1f[mi], b2f[nf][0], b2f[nf][1]);
#pragma unroll
            for (int mi = 0; mi < 2; mi++)
#pragma unroll
                for (int nf = 0; nf < 4; nf++)
                    mma_bf16(acc[mi][nf], a2f[mi], b1f[nf][0], b1f[nf][1]);
        }
        __syncthreads();
    }

    // epilogue: m16n8 frag: c0,c1 at (lane>>2, (lane&3)*2+{0,1}); c2,c3 at row+8
    const int group = lane >> 2, tid4 = lane & 3;
#pragma unroll
    for (int nf = 0; nf < 4; nf++) {
        int nb = n0 + wn * 32 + nf * 8 + tid4 * 2;
        float2 bv = *(const float2*)(bias + nb);
#pragma unroll
        for (int mi = 0; mi < 2; mi++) {
            int mb = m0 + wm * 32 + mi * 16 + group;
            float2 v0 = { acc[mi][nf][0] + bv.x, acc[mi][nf][1] + bv.y };
            float2 v1 = { acc[mi][nf][2] + bv.x, acc[mi][nf][3] + bv.y };
            *(float2*)(C + (size_t)mb * NN + nb) = v0;
            *(float2*)(C + (size_t)(mb + 8) * NN + nb) = v1;
        }
    }
}

// scan: h_t = relu(y_t + u h_{t-1}); writes bf16 split (or last slice)
template <bool WRITE_ALL>
__global__ __launch_bounds__(256) void scan_kernel(
    const float* __restrict__ y, __nv_bfloat16* __restrict__ o1,
    __nv_bfloat16* __restrict__ o2, float* __restrict__ olast,
    const float* __restrict__ u, float* __restrict__ gsum,
    float* __restrict__ gsumsq) {
    int idx = blockIdx.x * blockDim.x + threadIdx.x;
    int h = idx & (HH - 1);
    float uu = u[h];
    float s = 0.f, sum = 0.f, sq = 0.f;
    const float* p = y + idx;
#pragma unroll 1
    for (int t0 = 0; t0 < TT; t0 += 8) {
        float v[8];
#pragma unroll
        for (int j = 0; j < 8; j++) v[j] = p[(size_t)(t0 + j) * BH];
#pragma unroll
        for (int j = 0; j < 8; j++) {
            s = fmaxf(fmaf(uu, s, v[j]), 0.f);
            if (WRITE_ALL) {
                __nv_bfloat16 h1, h2; bsplit(s, h1, h2);
                o1[(size_t)(t0 + j) * BH + idx] = h1;
                o2[(size_t)(t0 + j) * BH + idx] = h2;
            }
            sum += s;
            sq = fmaf(s, s, sq);
        }
    }
    if (!WRITE_ALL) olast[idx] = s;
    atomicAdd(&gsum[h], sum);
    atomicAdd(&gsumsq[h], sq);
}

__global__ void final_kernel(const float* __restrict__ hl,
                             const float* __restrict__ Wout,
                             const float* __restrict__ bout,
                             float* __restrict__ out) {
    __shared__ float sh[HH];
    int b = blockIdx.x;
    for (int h = threadIdx.x; h < HH; h += blockDim.x)
        sh[h] = fmaf(hl[b * HH + h], g_scale[h], g_shift[h]);
    __syncthreads();
    int c = threadIdx.x;
    if (c < CC) {
        float acc = bout[c];
#pragma unroll 8
        for (int h = 0; h < HH; h++)
            acc = fmaf(sh[h], Wout[c * HH + h], acc);
        out[b * CC + c] = acc;
    }
}

extern "C" void kernel_launch(void* const* d_in, const int* in_sizes, int n_in,
                              void* d_out, int out_size) {
    const float* x     = (const float*)d_in[0];
    const float* W0    = (const float*)d_in[1];
    const float* b0    = (const float*)d_in[2];
    const float* Wh    = (const float*)d_in[3];
    const float* bh    = (const float*)d_in[4];
    const float* u     = (const float*)d_in[5];
    const float* gamma = (const float*)d_in[6];
    const float* beta  = (const float*)d_in[7];
    const float* Wout  = (const float*)d_in[8];
    const float* bout  = (const float*)d_in[9];
    float* out = (float*)d_out;

    float *Y, *beff, *sum, *sumsq, *hlast;
    __nv_bfloat16 *A1, *A2, *B1, *B2;
    cudaGetSymbolAddress((void**)&Y, g_Y);
    cudaGetSymbolAddress((void**)&A1, g_A1);
    cudaGetSymbolAddress((void**)&A2, g_A2);
    cudaGetSymbolAddress((void**)&B1, g_B1);
    cudaGetSymbolAddress((void**)&B2, g_B2);
    cudaGetSymbolAddress((void**)&beff, g_beff);
    cudaGetSymbolAddress((void**)&sum, g_sum);
    cudaGetSymbolAddress((void**)&sumsq, g_sumsq);
    cudaGetSymbolAddress((void**)&hlast, g_hlast);

    cudaFuncSetAttribute(gemm_tc, cudaFuncAttributeMaxDynamicSharedMemorySize, GSMEM_TOTAL);

    zero_stats_kernel<<<(LL * HH + 255) / 256, 256>>>();
    pad_x_kernel<<<(MM * K0P + 255) / 256, 256>>>(x);
    prep_w0_kernel<<<(HH * K0P + 255) / 256, 256>>>(W0, b0);

    dim3 ggrid(NN / BN, MM / BM);

    gemm_tc<<<ggrid, GT, GSMEM_TOTAL>>>(A1, A2, B1, B2, beff, Y, K0P);
    scan_kernel<true><<<BH / 256, 256>>>(Y, A1, A2, hlast, u, sum, sumsq);

    for (int l = 1; l < LL; l++) {
        const float* Wl  = Wh + (size_t)(l - 1) * HH * HH;
        const float* bhl = bh + (size_t)(l - 1) * HH;
        scale_shift_kernel<<<2, 256>>>(sum + (l - 1) * HH, sumsq + (l - 1) * HH,
                                       gamma + (l - 1) * HH, beta + (l - 1) * HH);
        fold_w_kernel<<<(HH * HH + 255) / 256, 256>>>(Wl);
        fold_bias_kernel<<<HH, 128>>>(Wl, bhl);
        gemm_tc<<<ggrid, GT, GSMEM_TOTAL>>>(A1, A2, B1, B2, beff, Y, HH);
        if (l < LL - 1)
            scan_kernel<true><<<BH / 256, 256>>>(Y, A1, A2, hlast, u + l * HH,
                                                 sum + l * HH, sumsq + l * HH);
        else
            scan_kernel<false><<<BH / 256, 256>>>(Y, A1, A2, hlast, u + l * HH,
                                                  sum + l * HH, sumsq + l * HH);
    }

    scale_shift_kernel<<<2, 256>>>(sum + (LL - 1) * HH, sumsq + (LL - 1) * HH,
                                   gamma + (LL - 1) * HH, beta + (LL - 1) * HH);
    final_kernel<<<BB, 64>>>(hlast, Wout, bout, out);
}

// round 6
// speedup vs baseline: 2.6318x; 1.2922x over previous
#include <cuda_runtime.h>
#include <cuda_fp16.h>
#include <cstdint>

#define TT 512
#define BB 128
#define HH 512
#define LL 6
#define CC 60
#define J3 75
#define K0P 128
#define BH (BB*HH)
#define MM (TT*BB)
#define NN 512
#define EPSBN 1e-5f

// GEMM tiling: BM=128, BN=128, BK=32, 512 threads (16 warps, 4x4 grid of 32x32 warp tiles)
#define BM 128
#define BN 128
#define BK 32
#define GT 512
#define NSTAGE 4
#define STAGE_BYTES 24576      // A(8K) + B1(8K) + B2(8K)
#define OFF_SA  0
#define OFF_SB1 8192
#define OFF_SB2 16384
#define GSMEM_TOTAL (NSTAGE*STAGE_BYTES)

__device__ float  g_Y[(size_t)MM * HH];
__device__ __half g_A[(size_t)MM * HH];     // activations, single fp16
__device__ __half g_B1[HH * HH];            // folded weight hi
__device__ __half g_B2[HH * HH];            // folded weight lo
__device__ float g_beff[HH];
__device__ float g_scale[HH];
__device__ float g_shift[HH];
__device__ float g_sum[LL * HH];
__device__ float g_sumsq[LL * HH];
__device__ float g_hlast[BH];

__device__ __forceinline__ uint32_t smem_u32(const void* p) {
    uint32_t a;
    asm("{ .reg .u64 t; cvta.to.shared.u64 t, %1; cvt.u32.u64 %0, t; }" : "=r"(a) : "l"(p));
    return a;
}
__device__ __forceinline__ uint32_t swz64(uint32_t off) { return off ^ ((off >> 3) & 0x30); }
__device__ __forceinline__ void cp16(uint32_t dst, const void* src) {
    asm volatile("cp.async.cg.shared.global [%0], [%1], 16;\n" :: "r"(dst), "l"(src));
}
__device__ __forceinline__ void cp_commit() { asm volatile("cp.async.commit_group;\n" ::: "memory"); }
template <int N> __device__ __forceinline__ void cp_wait() {
    asm volatile("cp.async.wait_group %0;\n" :: "n"(N) : "memory");
}
__device__ __forceinline__ void ldm_x4(uint32_t& r0, uint32_t& r1, uint32_t& r2, uint32_t& r3,
                                       uint32_t addr) {
    asm volatile("ldmatrix.sync.aligned.m8n8.x4.shared.b16 {%0,%1,%2,%3}, [%4];"
        : "=r"(r0), "=r"(r1), "=r"(r2), "=r"(r3) : "r"(addr));
}
__device__ __forceinline__ void mma_f16(float* c, const uint32_t* a, uint32_t b0, uint32_t b1) {
    asm volatile("mma.sync.aligned.m16n8k16.row.col.f32.f16.f16.f32 "
        "{%0,%1,%2,%3}, {%4,%5,%6,%7}, {%8,%9}, {%0,%1,%2,%3};"
        : "+f"(c[0]), "+f"(c[1]), "+f"(c[2]), "+f"(c[3])
        : "r"(a[0]), "r"(a[1]), "r"(a[2]), "r"(a[3]), "r"(b0), "r"(b1));
}
__device__ __forceinline__ void hsplit(float v, __half& h1, __half& h2) {
    h1 = __float2half_rn(v);
    h2 = __float2half_rn(v - __half2float(h1));
}

__global__ void zero_stats_kernel() {
    int i = blockIdx.x * blockDim.x + threadIdx.x;
    if (i < LL * HH) { g_sum[i] = 0.f; g_sumsq[i] = 0.f; }
}

__global__ void pad_x_kernel(const float* __restrict__ x) {
    int idx = blockIdx.x * blockDim.x + threadIdx.x;
    if (idx >= MM * K0P) return;
    int m = idx >> 7, k = idx & 127;
    float v = (k < J3) ? x[m * J3 + k] : 0.f;
    g_A[idx] = __float2half_rn(v);
}

__global__ void prep_w0_kernel(const float* __restrict__ W0, const float* __restrict__ b0) {
    int idx = blockIdx.x * blockDim.x + threadIdx.x;
    if (idx < HH * K0P) {
        int n = idx >> 7, k = idx & 127;
        float v = (k < J3) ? W0[n * J3 + k] : 0.f;
        __half h1, h2; hsplit(v, h1, h2);
        g_B1[idx] = h1; g_B2[idx] = h2;
    }
    if (idx < HH) g_beff[idx] = b0[idx];
}

__global__ void scale_shift_kernel(const float* __restrict__ sum,
                                   const float* __restrict__ sumsq,
                                   const float* __restrict__ gamma,
                                   const float* __restrict__ beta) {
    int h = blockIdx.x * blockDim.x + threadIdx.x;
    if (h >= HH) return;
    const float inv = 1.0f / (float)(TT * BB);
    float mean = sum[h] * inv;
    float var  = sumsq[h] * inv - mean * mean;
    float sc   = gamma[h] * rsqrtf(var + EPSBN);
    g_scale[h] = sc;
    g_shift[h] = beta[h] - mean * sc;
}

__global__ void fold_w_kernel(const float* __restrict__ W) {
    int idx = blockIdx.x * blockDim.x + threadIdx.x;
    if (idx >= HH * HH) return;
    int k = idx & (HH - 1);
    float v = W[idx] * g_scale[k];
    __half h1, h2; hsplit(v, h1, h2);
    g_B1[idx] = h1; g_B2[idx] = h2;
}

__global__ void fold_bias_kernel(const float* __restrict__ W, const float* __restrict__ bh) {
    int h = blockIdx.x;
    int tid = threadIdx.x;
    float acc = 0.f;
    for (int i = tid; i < HH; i += 128)
        acc = fmaf(W[h * HH + i], g_shift[i], acc);
    __shared__ float red[128];
    red[tid] = acc;
    __syncthreads();
    for (int s = 64; s > 0; s >>= 1) {
        if (tid < s) red[tid] += red[tid + s];
        __syncthreads();
    }
    if (tid == 0) g_beff[h] = bh[h] + red[0];
}

// C[M, n0:n0+128] = A[M,K] @ (B1+B2)[N,K]^T + bias  (fp16 A, 2-pass split B)
__global__ __launch_bounds__(GT, 1) void gemm_tc(
    const __half* __restrict__ A,
    const __half* __restrict__ B1, const __half* __restrict__ B2,
    const float* __restrict__ bias, float* __restrict__ C, int K) {
    extern __shared__ __align__(128) char smem[];
    const uint32_t sb = smem_u32(smem);
    const int tid = threadIdx.x, wid = tid >> 5, lane = tid & 31;
    const int n0 = blockIdx.x * BN;
    const int m0 = blockIdx.y * BM;
    const int NC = K / BK;
    const int wm = wid & 3;       // 4 m-warps -> 32 rows each
    const int wn = wid >> 2;      // 4 n-warps -> 32 cols each

    float acc[2][4][4];
#pragma unroll
    for (int i = 0; i < 2; i++)
#pragma unroll
        for (int j = 0; j < 4; j++)
#pragma unroll
            for (int q = 0; q < 4; q++) acc[i][j][q] = 0.f;

    auto load_stage = [&](int c, int s) {
        const uint32_t st = sb + s * STAGE_BYTES;
        const int k0 = c * BK;
#pragma unroll
        for (int i = 0; i < 3; i++) {
            int g = i * GT + tid;            // 0..1535
            int arr = g >> 9;                // 0:A 1:B1 2:B2
            int rem = g & 511;
            int row = rem >> 2, ch = rem & 3;
            const __half* src;
            if (arr == 0)      src = A  + ((size_t)(m0 + row) * K + k0 + ch * 8);
            else if (arr == 1) src = B1 + ((size_t)(n0 + row) * K + k0 + ch * 8);
            else               src = B2 + ((size_t)(n0 + row) * K + k0 + ch * 8);
            cp16(st + arr * 8192 + swz64((uint32_t)(row * 64 + ch * 16)), src);
        }
        cp_commit();
    };

    // prologue
#pragma unroll
    for (int s = 0; s < NSTAGE - 1; s++) {
        if (s < NC) load_stage(s, s); else cp_commit();
    }

    for (int c = 0; c < NC; c++) {
        cp_wait<NSTAGE - 2>();
        __syncthreads();
        if (c + NSTAGE - 1 < NC) load_stage(c + NSTAGE - 1, (c + NSTAGE - 1) & (NSTAGE - 1));
        else cp_commit();

        const uint32_t st = sb + (c & (NSTAGE - 1)) * STAGE_BYTES;
#pragma unroll
        for (int ks = 0; ks < 2; ks++) {
            const uint32_t cb = ks * 32 + (lane >> 4) * 16;
            uint32_t af[2][4];
#pragma unroll
            for (int mi = 0; mi < 2; mi++) {
                uint32_t row = wm * 32 + mi * 16 + (lane & 15);
                uint32_t off = swz64(row * 64 + cb);
                ldm_x4(af[mi][0], af[mi][1], af[mi][2], af[mi][3], st + OFF_SA + off);
            }
            uint32_t b1f[4][2], b2f[4][2];
#pragma unroll
            for (int ni = 0; ni < 2; ni++) {
                uint32_t row = wn * 32 + ni * 16 + (lane & 15);
                uint32_t off = swz64(row * 64 + cb);
                uint32_t r0, r1, r2, r3;
                ldm_x4(r0, r1, r2, r3, st + OFF_SB1 + off);
                b1f[2*ni][0] = r0; b1f[2*ni][1] = r2;
                b1f[2*ni+1][0] = r1; b1f[2*ni+1][1] = r3;
                ldm_x4(r0, r1, r2, r3, st + OFF_SB2 + off);
                b2f[2*ni][0] = r0; b2f[2*ni][1] = r2;
                b2f[2*ni+1][0] = r1; b2f[2*ni+1][1] = r3;
            }
            // two passes
#pragma unroll
            for (int mi = 0; mi < 2; mi++)
#pragma unroll
                for (int nf = 0; nf < 4; nf++)
                    mma_f16(acc[mi][nf], af[mi], b1f[nf][0], b1f[nf][1]);
#pragma unroll
            for (int mi = 0; mi < 2; mi++)
#pragma unroll
                for (int nf = 0; nf < 4; nf++)
                    mma_f16(acc[mi][nf], af[mi], b2f[nf][0], b2f[nf][1]);
        }
        __syncthreads();
    }

    // epilogue: m16n8 frag: c0,c1 at (lane>>2, (lane&3)*2+{0,1}); c2,c3 at row+8
    const int group = lane >> 2, tid4 = lane & 3;
#pragma unroll
    for (int nf = 0; nf < 4; nf++) {
        int nb = n0 + wn * 32 + nf * 8 + tid4 * 2;
        float2 bv = *(const float2*)(bias + nb);
#pragma unroll
        for (int mi = 0; mi < 2; mi++) {
            int mb = m0 + wm * 32 + mi * 16 + group;
            float2 v0 = { acc[mi][nf][0] + bv.x, acc[mi][nf][1] + bv.y };
            float2 v1 = { acc[mi][nf][2] + bv.x, acc[mi][nf][3] + bv.y };
            *(float2*)(C + (size_t)mb * NN + nb) = v0;
            *(float2*)(C + (size_t)(mb + 8) * NN + nb) = v1;
        }
    }
}

// scan: h_t = relu(y_t + u h_{t-1}); writes fp16 h (or last slice fp32)
template <bool WRITE_ALL>
__global__ __launch_bounds__(256) void scan_kernel(
    const float* __restrict__ y, __half* __restrict__ o,
    float* __restrict__ olast,
    const float* __restrict__ u, float* __restrict__ gsum,
    float* __restrict__ gsumsq) {
    int idx = blockIdx.x * blockDim.x + threadIdx.x;
    int h = idx & (HH - 1);
    float uu = u[h];
    float s = 0.f, sum = 0.f, sq = 0.f;
    const float* p = y + idx;
#pragma unroll 1
    for (int t0 = 0; t0 < TT; t0 += 8) {
        float v[8];
#pragma unroll
        for (int j = 0; j < 8; j++) v[j] = p[(size_t)(t0 + j) * BH];
#pragma unroll
        for (int j = 0; j < 8; j++) {
            s = fmaxf(fmaf(uu, s, v[j]), 0.f);
            if (WRITE_ALL) o[(size_t)(t0 + j) * BH + idx] = __float2half_rn(s);
            sum += s;
            sq = fmaf(s, s, sq);
        }
    }
    if (!WRITE_ALL) olast[idx] = s;
    atomicAdd(&gsum[h], sum);
    atomicAdd(&gsumsq[h], sq);
}

__global__ void final_kernel(const float* __restrict__ hl,
                             const float* __restrict__ Wout,
                             const float* __restrict__ bout,
                             float* __restrict__ out) {
    __shared__ float sh[HH];
    int b = blockIdx.x;
    for (int h = threadIdx.x; h < HH; h += blockDim.x)
        sh[h] = fmaf(hl[b * HH + h], g_scale[h], g_shift[h]);
    __syncthreads();
    int c = threadIdx.x;
    if (c < CC) {
        float acc = bout[c];
#pragma unroll 8
        for (int h = 0; h < HH; h++)
            acc = fmaf(sh[h], Wout[c * HH + h], acc);
        out[b * CC + c] = acc;
    }
}

extern "C" void kernel_launch(void* const* d_in, const int* in_sizes, int n_in,
                              void* d_out, int out_size) {
    const float* x     = (const float*)d_in[0];
    const float* W0    = (const float*)d_in[1];
    const float* b0    = (const float*)d_in[2];
    const float* Wh    = (const float*)d_in[3];
    const float* bh    = (const float*)d_in[4];
    const float* u     = (const float*)d_in[5];
    const float* gamma = (const float*)d_in[6];
    const float* beta  = (const float*)d_in[7];
    const float* Wout  = (const float*)d_in[8];
    const float* bout  = (const float*)d_in[9];
    float* out = (float*)d_out;

    float *Y, *beff, *sum, *sumsq, *hlast;
    __half *A, *B1, *B2;
    cudaGetSymbolAddress((void**)&Y, g_Y);
    cudaGetSymbolAddress((void**)&A, g_A);
    cudaGetSymbolAddress((void**)&B1, g_B1);
    cudaGetSymbolAddress((void**)&B2, g_B2);
    cudaGetSymbolAddress((void**)&beff, g_beff);
    cudaGetSymbolAddress((void**)&sum, g_sum);
    cudaGetSymbolAddress((void**)&sumsq, g_sumsq);
    cudaGetSymbolAddress((void**)&hlast, g_hlast);

    cudaFuncSetAttribute(gemm_tc, cudaFuncAttributeMaxDynamicSharedMemorySize, GSMEM_TOTAL);

    zero_stats_kernel<<<(LL * HH + 255) / 256, 256>>>();
    pad_x_kernel<<<(MM * K0P + 255) / 256, 256>>>(x);
    prep_w0_kernel<<<(HH * K0P + 255) / 256, 256>>>(W0, b0);

    dim3 ggrid(NN / BN, MM / BM);

    gemm_tc<<<ggrid, GT, GSMEM_TOTAL>>>(A, B1, B2, beff, Y, K0P);
    scan_kernel<true><<<BH / 256, 256>>>(Y, A, hlast, u, sum, sumsq);

    for (int l = 1; l < LL; l++) {
        const float* Wl  = Wh + (size_t)(l - 1) * HH * HH;
        const float* bhl = bh + (size_t)(l - 1) * HH;
        scale_shift_kernel<<<2, 256>>>(sum + (l - 1) * HH, sumsq + (l - 1) * HH,
                                       gamma + (l - 1) * HH, beta + (l - 1) * HH);
        fold_w_kernel<<<(HH * HH + 255) / 256, 256>>>(Wl);
        fold_bias_kernel<<<HH, 128>>>(Wl, bhl);
        gemm_tc<<<ggrid, GT, GSMEM_TOTAL>>>(A, B1, B2, beff, Y, HH);
        if (l < LL - 1)
            scan_kernel<true><<<BH / 256, 256>>>(Y, A, hlast, u + l * HH,
                                                 sum + l * HH, sumsq + l * HH);
        else
            scan_kernel<false><<<BH / 256, 256>>>(Y, A, hlast, u + l * HH,
                                                  sum + l * HH, sumsq + l * HH);
    }

    scale_shift_kernel<<<2, 256>>>(sum + (LL - 1) * HH, sumsq + (LL - 1) * HH,
                                   gamma + (LL - 1) * HH, beta + (LL - 1) * HH);
    final_kernel<<<BB, 64>>>(hlast, Wout, bout, out);
}

// round 7
// speedup vs baseline: 3.1893x; 1.2118x over previous
#include <cuda_runtime.h>
#include <cuda_fp16.h>
#include <cstdint>

#define TT 512
#define BB 128
#define HH 512
#define LL 6
#define CC 60
#define J3 75
#define K0P 128
#define BH (BB*HH)
#define MM (TT*BB)
#define NN 512
#define EPSBN 1e-5f

// GEMM tiling: BM=128, BN=128, BK=32, 256 threads (8 warps, 2x4 grid of 64x32 warp tiles)
#define BM 128
#define BN 128
#define BK 32
#define GT 256
#define NSTAGE 4
#define STAGE_BYTES 24576      // A(8K) + B1(8K) + B2(8K)
#define OFF_SA  0
#define OFF_SB1 8192
#define OFF_SB2 16384
#define GSMEM_TOTAL (NSTAGE*STAGE_BYTES)

__device__ float  g_Y[(size_t)MM * HH];
__device__ __half g_A[(size_t)MM * HH];     // activations, single fp16
__device__ __half g_B1[HH * HH];            // folded weight hi
__device__ __half g_B2[HH * HH];            // folded weight lo
__device__ float g_beff[HH];
__device__ float g_scale[HH];
__device__ float g_shift[HH];
__device__ float g_sum[LL * HH];
__device__ float g_sumsq[LL * HH];
__device__ float g_hlast[BH];

__device__ __forceinline__ uint32_t smem_u32(const void* p) {
    uint32_t a;
    asm("{ .reg .u64 t; cvta.to.shared.u64 t, %1; cvt.u32.u64 %0, t; }" : "=r"(a) : "l"(p));
    return a;
}
__device__ __forceinline__ uint32_t swz64(uint32_t off) { return off ^ ((off >> 3) & 0x30); }
__device__ __forceinline__ void cp16(uint32_t dst, const void* src) {
    asm volatile("cp.async.cg.shared.global [%0], [%1], 16;\n" :: "r"(dst), "l"(src));
}
__device__ __forceinline__ void cp_commit() { asm volatile("cp.async.commit_group;\n" ::: "memory"); }
template <int N> __device__ __forceinline__ void cp_wait() {
    asm volatile("cp.async.wait_group %0;\n" :: "n"(N) : "memory");
}
__device__ __forceinline__ void ldm_x4(uint32_t& r0, uint32_t& r1, uint32_t& r2, uint32_t& r3,
                                       uint32_t addr) {
    asm volatile("ldmatrix.sync.aligned.m8n8.x4.shared.b16 {%0,%1,%2,%3}, [%4];"
        : "=r"(r0), "=r"(r1), "=r"(r2), "=r"(r3) : "r"(addr));
}
__device__ __forceinline__ void mma_f16(float* c, const uint32_t* a, uint32_t b0, uint32_t b1) {
    asm volatile("mma.sync.aligned.m16n8k16.row.col.f32.f16.f16.f32 "
        "{%0,%1,%2,%3}, {%4,%5,%6,%7}, {%8,%9}, {%0,%1,%2,%3};"
        : "+f"(c[0]), "+f"(c[1]), "+f"(c[2]), "+f"(c[3])
        : "r"(a[0]), "r"(a[1]), "r"(a[2]), "r"(a[3]), "r"(b0), "r"(b1));
}
__device__ __forceinline__ void hsplit(float v, __half& h1, __half& h2) {
    h1 = __float2half_rn(v);
    h2 = __float2half_rn(v - __half2float(h1));
}

__global__ void zero_stats_kernel() {
    int i = blockIdx.x * blockDim.x + threadIdx.x;
    if (i < LL * HH) { g_sum[i] = 0.f; g_sumsq[i] = 0.f; }
}

__global__ void pad_x_kernel(const float* __restrict__ x) {
    int idx = blockIdx.x * blockDim.x + threadIdx.x;
    if (idx >= MM * K0P) return;
    int m = idx >> 7, k = idx & 127;
    float v = (k < J3) ? x[m * J3 + k] : 0.f;
    g_A[idx] = __float2half_rn(v);
}

__global__ void prep_w0_kernel(const float* __restrict__ W0, const float* __restrict__ b0) {
    int idx = blockIdx.x * blockDim.x + threadIdx.x;
    if (idx < HH * K0P) {
        int n = idx >> 7, k = idx & 127;
        float v = (k < J3) ? W0[n * J3 + k] : 0.f;
        __half h1, h2; hsplit(v, h1, h2);
        g_B1[idx] = h1; g_B2[idx] = h2;
    }
    if (idx < HH) g_beff[idx] = b0[idx];
}

__global__ void scale_shift_kernel(const float* __restrict__ sum,
                                   const float* __restrict__ sumsq,
                                   const float* __restrict__ gamma,
                                   const float* __restrict__ beta) {
    int h = blockIdx.x * blockDim.x + threadIdx.x;
    if (h >= HH) return;
    const float inv = 1.0f / (float)(TT * BB);
    float mean = sum[h] * inv;
    float var  = sumsq[h] * inv - mean * mean;
    float sc   = gamma[h] * rsqrtf(var + EPSBN);
    g_scale[h] = sc;
    g_shift[h] = beta[h] - mean * sc;
}

// one block per output row h: compute BN affine in smem, fold into W row + bias
__global__ __launch_bounds__(HH) void fold_all_kernel(
    const float* __restrict__ W, const float* __restrict__ bh,
    const float* __restrict__ sum, const float* __restrict__ sumsq,
    const float* __restrict__ gamma, const float* __restrict__ beta) {
    __shared__ float s_scale[HH], s_shift[HH], red[HH];
    const int t = threadIdx.x;   // 512
    {
        const float inv = 1.0f / (float)(TT * BB);
        float mean = sum[t] * inv;
        float var  = sumsq[t] * inv - mean * mean;
        float sc   = gamma[t] * rsqrtf(var + EPSBN);
        s_scale[t] = sc;
        s_shift[t] = beta[t] - mean * sc;
    }
    __syncthreads();
    const int h = blockIdx.x;
    float w = W[h * HH + t];
    float v = w * s_scale[t];
    __half h1, h2; hsplit(v, h1, h2);
    g_B1[h * HH + t] = h1;
    g_B2[h * HH + t] = h2;
    red[t] = w * s_shift[t];
    __syncthreads();
    for (int s = HH / 2; s > 0; s >>= 1) {
        if (t < s) red[t] += red[t + s];
        __syncthreads();
    }
    if (t == 0) g_beff[h] = bh[h] + red[0];
}

// C[M, n0:n0+128] = A[M,K] @ (B1+B2)[N,K]^T + bias  (fp16 A, 2-pass split B)
// 256 threads, 2x4 warp grid, 64x32 warp tiles, 2 CTAs/SM
__global__ __launch_bounds__(GT, 2) void gemm_tc(
    const __half* __restrict__ A,
    const __half* __restrict__ B1, const __half* __restrict__ B2,
    const float* __restrict__ bias, float* __restrict__ C, int K) {
    extern __shared__ __align__(128) char smem[];
    const uint32_t sb = smem_u32(smem);
    const int tid = threadIdx.x, wid = tid >> 5, lane = tid & 31;
    const int n0 = blockIdx.x * BN;
    const int m0 = blockIdx.y * BM;
    const int NC = K / BK;
    const int wm = wid & 1;       // 2 m-warps -> 64 rows each
    const int wn = wid >> 1;      // 4 n-warps -> 32 cols each

    float acc[4][4][4];
#pragma unroll
    for (int i = 0; i < 4; i++)
#pragma unroll
        for (int j = 0; j < 4; j++)
#pragma unroll
            for (int q = 0; q < 4; q++) acc[i][j][q] = 0.f;

    auto load_stage = [&](int c, int s) {
        const uint32_t st = sb + s * STAGE_BYTES;
        const int k0 = c * BK;
#pragma unroll
        for (int i = 0; i < 6; i++) {
            int g = i * GT + tid;            // 0..1535
            int arr = g >> 9;                // 0:A 1:B1 2:B2
            int rem = g & 511;
            int row = rem >> 2, ch = rem & 3;
            const __half* src;
            if (arr == 0)      src = A  + ((size_t)(m0 + row) * K + k0 + ch * 8);
            else if (arr == 1) src = B1 + ((size_t)(n0 + row) * K + k0 + ch * 8);
            else               src = B2 + ((size_t)(n0 + row) * K + k0 + ch * 8);
            cp16(st + arr * 8192 + swz64((uint32_t)(row * 64 + ch * 16)), src);
        }
        cp_commit();
    };

    // prologue
#pragma unroll
    for (int s = 0; s < NSTAGE - 1; s++) {
        if (s < NC) load_stage(s, s); else cp_commit();
    }

    for (int c = 0; c < NC; c++) {
        cp_wait<NSTAGE - 2>();
        __syncthreads();
        if (c + NSTAGE - 1 < NC) load_stage(c + NSTAGE - 1, (c + NSTAGE - 1) & (NSTAGE - 1));
        else cp_commit();

        const uint32_t st = sb + (c & (NSTAGE - 1)) * STAGE_BYTES;
#pragma unroll
        for (int ks = 0; ks < 2; ks++) {
            const uint32_t cb = ks * 32 + (lane >> 4) * 16;
            uint32_t af[4][4];
#pragma unroll
            for (int mi = 0; mi < 4; mi++) {
                uint32_t row = wm * 64 + mi * 16 + (lane & 15);
                uint32_t off = swz64(row * 64 + cb);
                ldm_x4(af[mi][0], af[mi][1], af[mi][2], af[mi][3], st + OFF_SA + off);
            }
            uint32_t b1f[4][2], b2f[4][2];
#pragma unroll
            for (int ni = 0; ni < 2; ni++) {
                uint32_t row = wn * 32 + ni * 16 + (lane & 15);
                uint32_t off = swz64(row * 64 + cb);
                uint32_t r0, r1, r2, r3;
                ldm_x4(r0, r1, r2, r3, st + OFF_SB1 + off);
                b1f[2*ni][0] = r0; b1f[2*ni][1] = r2;
                b1f[2*ni+1][0] = r1; b1f[2*ni+1][1] = r3;
                ldm_x4(r0, r1, r2, r3, st + OFF_SB2 + off);
                b2f[2*ni][0] = r0; b2f[2*ni][1] = r2;
                b2f[2*ni+1][0] = r1; b2f[2*ni+1][1] = r3;
            }
            // two passes over the 4x4 fragment grid
#pragma unroll
            for (int mi = 0; mi < 4; mi++)
#pragma unroll
                for (int nf = 0; nf < 4; nf++)
                    mma_f16(acc[mi][nf], af[mi], b1f[nf][0], b1f[nf][1]);
#pragma unroll
            for (int mi = 0; mi < 4; mi++)
#pragma unroll
                for (int nf = 0; nf < 4; nf++)
                    mma_f16(acc[mi][nf], af[mi], b2f[nf][0], b2f[nf][1]);
        }
        __syncthreads();
    }

    // epilogue: m16n8 frag: c0,c1 at (lane>>2, (lane&3)*2+{0,1}); c2,c3 at row+8
    const int group = lane >> 2, tid4 = lane & 3;
#pragma unroll
    for (int nf = 0; nf < 4; nf++) {
        int nb = n0 + wn * 32 + nf * 8 + tid4 * 2;
        float2 bv = *(const float2*)(bias + nb);
#pragma unroll
        for (int mi = 0; mi < 4; mi++) {
            int mb = m0 + wm * 64 + mi * 16 + group;
            float2 v0 = { acc[mi][nf][0] + bv.x, acc[mi][nf][1] + bv.y };
            float2 v1 = { acc[mi][nf][2] + bv.x, acc[mi][nf][3] + bv.y };
            *(float2*)(C + (size_t)mb * NN + nb) = v0;
            *(float2*)(C + (size_t)(mb + 8) * NN + nb) = v1;
        }
    }
}

// scan: h_t = relu(y_t + u h_{t-1}); writes fp16 h (or last slice fp32)
template <bool WRITE_ALL>
__global__ __launch_bounds__(256) void scan_kernel(
    const float* __restrict__ y, __half* __restrict__ o,
    float* __restrict__ olast,
    const float* __restrict__ u, float* __restrict__ gsum,
    float* __restrict__ gsumsq) {
    int idx = blockIdx.x * blockDim.x + threadIdx.x;
    int h = idx & (HH - 1);
    float uu = u[h];
    float s = 0.f, sum = 0.f, sq = 0.f;
    const float* p = y + idx;
#pragma unroll 1
    for (int t0 = 0; t0 < TT; t0 += 16) {
        float v[16];
#pragma unroll
        for (int j = 0; j < 16; j++) v[j] = p[(size_t)(t0 + j) * BH];
#pragma unroll
        for (int j = 0; j < 16; j++) {
            s = fmaxf(fmaf(uu, s, v[j]), 0.f);
            if (WRITE_ALL) o[(size_t)(t0 + j) * BH + idx] = __float2half_rn(s);
            sum += s;
            sq = fmaf(s, s, sq);
        }
    }
    if (!WRITE_ALL) olast[idx] = s;
    atomicAdd(&gsum[h], sum);
    atomicAdd(&gsumsq[h], sq);
}

__global__ void final_kernel(const float* __restrict__ hl,
                             const float* __restrict__ Wout,
                             const float* __restrict__ bout,
                             float* __restrict__ out) {
    __shared__ float sh[HH];
    int b = blockIdx.x;
    for (int h = threadIdx.x; h < HH; h += blockDim.x)
        sh[h] = fmaf(hl[b * HH + h], g_scale[h], g_shift[h]);
    __syncthreads();
    int c = threadIdx.x;
    if (c < CC) {
        float acc = bout[c];
#pragma unroll 8
        for (int h = 0; h < HH; h++)
            acc = fmaf(sh[h], Wout[c * HH + h], acc);
        out[b * CC + c] = acc;
    }
}

extern "C" void kernel_launch(void* const* d_in, const int* in_sizes, int n_in,
                              void* d_out, int out_size) {
    const float* x     = (const float*)d_in[0];
    const float* W0    = (const float*)d_in[1];
    const float* b0    = (const float*)d_in[2];
    const float* Wh    = (const float*)d_in[3];
    const float* bh    = (const float*)d_in[4];
    const float* u     = (const float*)d_in[5];
    const float* gamma = (const float*)d_in[6];
    const float* beta  = (const float*)d_in[7];
    const float* Wout  = (const float*)d_in[8];
    const float* bout  = (const float*)d_in[9];
    float* out = (float*)d_out;

    float *Y, *beff, *sum, *sumsq, *hlast;
    __half *A, *B1, *B2;
    cudaGetSymbolAddress((void**)&Y, g_Y);
    cudaGetSymbolAddress((void**)&A, g_A);
    cudaGetSymbolAddress((void**)&B1, g_B1);
    cudaGetSymbolAddress((void**)&B2, g_B2);
    cudaGetSymbolAddress((void**)&beff, g_beff);
    cudaGetSymbolAddress((void**)&sum, g_sum);
    cudaGetSymbolAddress((void**)&sumsq, g_sumsq);
    cudaGetSymbolAddress((void**)&hlast, g_hlast);

    cudaFuncSetAttribute(gemm_tc, cudaFuncAttributeMaxDynamicSharedMemorySize, GSMEM_TOTAL);

    zero_stats_kernel<<<(LL * HH + 255) / 256, 256>>>();
    pad_x_kernel<<<(MM * K0P + 255) / 256, 256>>>(x);
    prep_w0_kernel<<<(HH * K0P + 255) / 256, 256>>>(W0, b0);

    dim3 ggrid(NN / BN, MM / BM);

    gemm_tc<<<ggrid, GT, GSMEM_TOTAL>>>(A, B1, B2, beff, Y, K0P);
    scan_kernel<true><<<BH / 256, 256>>>(Y, A, hlast, u, sum, sumsq);

    for (int l = 1; l < LL; l++) {
        const float* Wl  = Wh + (size_t)(l - 1) * HH * HH;
        const float* bhl = bh + (size_t)(l - 1) * HH;
        fold_all_kernel<<<HH, HH>>>(Wl, bhl, sum + (l - 1) * HH, sumsq + (l - 1) * HH,
                                    gamma + (l - 1) * HH, beta + (l - 1) * HH);
        gemm_tc<<<ggrid, GT, GSMEM_TOTAL>>>(A, B1, B2, beff, Y, HH);
        if (l < LL - 1)
            scan_kernel<true><<<BH / 256, 256>>>(Y, A, hlast, u + l * HH,
                                                 sum + l * HH, sumsq + l * HH);
        else
            scan_kernel<false><<<BH / 256, 256>>>(Y, A, hlast, u + l * HH,
                                                  sum + l * HH, sumsq + l * HH);
    }

    scale_shift_kernel<<<2, 256>>>(sum + (LL - 1) * HH, sumsq + (LL - 1) * HH,
                                   gamma + (LL - 1) * HH, beta + (LL - 1) * HH);
    final_kernel<<<BB, 64>>>(hlast, Wout, bout, out);
}

// round 8
// speedup vs baseline: 3.2965x; 1.0336x over previous
#include <cuda_runtime.h>
#include <cuda_fp16.h>
#include <cstdint>

#define TT 512
#define BB 128
#define HH 512
#define LL 6
#define CC 60
#define J3 75
#define K0P 128
#define BH (BB*HH)
#define MM (TT*BB)
#define NN 512
#define EPSBN 1e-5f

// fused layer kernel tiling: per CTA: one b, 128 h-cols, 4 t-chunks of 128
#define BM 128              // t-chunk rows
#define BN 128              // h columns per CTA
#define BK 32
#define GT 256
#define NSTAGE 3
#define STAGE_BYTES 24576   // A(8K)+B1(8K)+B2(8K)
#define OFF_SA  0
#define OFF_SB1 8192
#define OFF_SB2 16384
#define SCAN_STRIDE 136     // floats per row (bank-shift 8)
#define FSMEM (NSTAGE*STAGE_BYTES)   // 73728 >= 128*136*4 = 69632 (scanbuf overlays stages)

__device__ __half g_Aping[(size_t)MM * HH];
__device__ __half g_Apong[(size_t)MM * HH];
__device__ __half g_B1[HH * HH];
__device__ __half g_B2[HH * HH];
__device__ float g_beff[HH];
__device__ float g_scale[HH];
__device__ float g_shift[HH];
__device__ float g_sum[LL * HH];
__device__ float g_sumsq[LL * HH];
__device__ float g_hlast[BH];

__device__ __forceinline__ uint32_t smem_u32(const void* p) {
    uint32_t a;
    asm("{ .reg .u64 t; cvta.to.shared.u64 t, %1; cvt.u32.u64 %0, t; }" : "=r"(a) : "l"(p));
    return a;
}
__device__ __forceinline__ uint32_t swz64(uint32_t off) { return off ^ ((off >> 3) & 0x30); }
__device__ __forceinline__ void cp16(uint32_t dst, const void* src) {
    asm volatile("cp.async.cg.shared.global [%0], [%1], 16;\n" :: "r"(dst), "l"(src));
}
__device__ __forceinline__ void cp_commit() { asm volatile("cp.async.commit_group;\n" ::: "memory"); }
template <int N> __device__ __forceinline__ void cp_wait() {
    asm volatile("cp.async.wait_group %0;\n" :: "n"(N) : "memory");
}
__device__ __forceinline__ void ldm_x4(uint32_t& r0, uint32_t& r1, uint32_t& r2, uint32_t& r3,
                                       uint32_t addr) {
    asm volatile("ldmatrix.sync.aligned.m8n8.x4.shared.b16 {%0,%1,%2,%3}, [%4];"
        : "=r"(r0), "=r"(r1), "=r"(r2), "=r"(r3) : "r"(addr));
}
__device__ __forceinline__ void mma_f16(float* c, const uint32_t* a, uint32_t b0, uint32_t b1) {
    asm volatile("mma.sync.aligned.m16n8k16.row.col.f32.f16.f16.f32 "
        "{%0,%1,%2,%3}, {%4,%5,%6,%7}, {%8,%9}, {%0,%1,%2,%3};"
        : "+f"(c[0]), "+f"(c[1]), "+f"(c[2]), "+f"(c[3])
        : "r"(a[0]), "r"(a[1]), "r"(a[2]), "r"(a[3]), "r"(b0), "r"(b1));
}
__device__ __forceinline__ void hsplit(float v, __half& h1, __half& h2) {
    h1 = __float2half_rn(v);
    h2 = __float2half_rn(v - __half2float(h1));
}

__global__ void zero_stats_kernel() {
    int i = blockIdx.x * blockDim.x + threadIdx.x;
    if (i < LL * HH) { g_sum[i] = 0.f; g_sumsq[i] = 0.f; }
}

__global__ void pad_x_kernel(const float* __restrict__ x) {
    int idx = blockIdx.x * blockDim.x + threadIdx.x;
    if (idx >= MM * K0P) return;
    int m = idx >> 7, k = idx & 127;
    float v = (k < J3) ? x[m * J3 + k] : 0.f;
    g_Aping[idx] = __float2half_rn(v);
}

__global__ void prep_w0_kernel(const float* __restrict__ W0, const float* __restrict__ b0) {
    int idx = blockIdx.x * blockDim.x + threadIdx.x;
    if (idx < HH * K0P) {
        int n = idx >> 7, k = idx & 127;
        float v = (k < J3) ? W0[n * J3 + k] : 0.f;
        __half h1, h2; hsplit(v, h1, h2);
        g_B1[idx] = h1; g_B2[idx] = h2;
    }
    if (idx < HH) g_beff[idx] = b0[idx];
}

__global__ void scale_shift_kernel(const float* __restrict__ sum,
                                   const float* __restrict__ sumsq,
                                   const float* __restrict__ gamma,
                                   const float* __restrict__ beta) {
    int h = blockIdx.x * blockDim.x + threadIdx.x;
    if (h >= HH) return;
    const float inv = 1.0f / (float)(TT * BB);
    float mean = sum[h] * inv;
    float var  = sumsq[h] * inv - mean * mean;
    float sc   = gamma[h] * rsqrtf(var + EPSBN);
    g_scale[h] = sc;
    g_shift[h] = beta[h] - mean * sc;
}

// one block per output row h: BN affine in smem, fold into W row + bias
__global__ __launch_bounds__(HH) void fold_all_kernel(
    const float* __restrict__ W, const float* __restrict__ bh,
    const float* __restrict__ sum, const float* __restrict__ sumsq,
    const float* __restrict__ gamma, const float* __restrict__ beta) {
    __shared__ float s_scale[HH], s_shift[HH], red[HH];
    const int t = threadIdx.x;
    {
        const float inv = 1.0f / (float)(TT * BB);
        float mean = sum[t] * inv;
        float var  = sumsq[t] * inv - mean * mean;
        float sc   = gamma[t] * rsqrtf(var + EPSBN);
        s_scale[t] = sc;
        s_shift[t] = beta[t] - mean * sc;
    }
    __syncthreads();
    const int h = blockIdx.x;
    float w = W[h * HH + t];
    float v = w * s_scale[t];
    __half h1, h2; hsplit(v, h1, h2);
    g_B1[h * HH + t] = h1;
    g_B2[h * HH + t] = h2;
    red[t] = w * s_shift[t];
    __syncthreads();
    for (int s = HH / 2; s > 0; s >>= 1) {
        if (t < s) red[t] += red[t + s];
        __syncthreads();
    }
    if (t == 0) g_beff[h] = bh[h] + red[0];
}

// Fused layer: per CTA (n-tile, b): for 4 t-chunks: GEMM 128x128 -> smem -> scan
template <bool WRITE_NEXT>
__global__ __launch_bounds__(GT, 2) void layer_fused(
    const __half* __restrict__ A,
    const __half* __restrict__ B1, const __half* __restrict__ B2,
    const float* __restrict__ bias, const float* __restrict__ u,
    __half* __restrict__ Anext, float* __restrict__ hlast,
    float* __restrict__ gsum, float* __restrict__ gsumsq, int K) {
    extern __shared__ __align__(128) char smem[];
    const uint32_t sb = smem_u32(smem);
    float* scanbuf = (float*)smem;                    // overlays pipeline stages
    const int tid = threadIdx.x, wid = tid >> 5, lane = tid & 31;
    const int n0 = blockIdx.x * BN;
    const int b  = blockIdx.y;
    const int NC = K / BK;
    const int wm = wid & 1;        // 2 m-warps -> 64 t-rows each
    const int wn = wid >> 1;       // 4 n-warps -> 32 h-cols each

    // persistent scan state (threads 0..127 own one h-col)
    float s_state = 0.f, l_sum = 0.f, l_sq = 0.f, uu = 0.f, bb = 0.f;
    if (tid < 128) { uu = u[n0 + tid]; bb = bias[n0 + tid]; }

    for (int tc = 0; tc < 4; tc++) {
        float acc[4][4][4];
#pragma unroll
        for (int i = 0; i < 4; i++)
#pragma unroll
            for (int j = 0; j < 4; j++)
#pragma unroll
                for (int q = 0; q < 4; q++) acc[i][j][q] = 0.f;

        auto load_stage = [&](int c, int st_i) {
            const uint32_t st = sb + st_i * STAGE_BYTES;
            const int k0 = c * BK;
#pragma unroll
            for (int i = 0; i < 6; i++) {
                int g = i * GT + tid;            // 0..1535
                int arr = g >> 9;                // 0:A 1:B1 2:B2
                int rem = g & 511;
                int row = rem >> 2, ch = rem & 3;
                const __half* src;
                if (arr == 0) {
                    int grow = (tc * 128 + row) * BB + b;
                    src = A + ((size_t)grow * K + k0 + ch * 8);
                } else if (arr == 1) {
                    src = B1 + ((size_t)(n0 + row) * K + k0 + ch * 8);
                } else {
                    src = B2 + ((size_t)(n0 + row) * K + k0 + ch * 8);
                }
                cp16(st + arr * 8192 + swz64((uint32_t)(row * 64 + ch * 16)), src);
            }
            cp_commit();
        };

        load_stage(0, 0);
        load_stage(1, 1);

        for (int c = 0; c < NC; c++) {
            cp_wait<1>();
            __syncthreads();
            if (c + 2 < NC) load_stage(c + 2, (c + 2) % NSTAGE);
            else cp_commit();

            const uint32_t st = sb + (c % NSTAGE) * STAGE_BYTES;
#pragma unroll
            for (int ks = 0; ks < 2; ks++) {
                const uint32_t cb = ks * 32 + (lane >> 4) * 16;
                uint32_t af[4][4];
#pragma unroll
                for (int mi = 0; mi < 4; mi++) {
                    uint32_t row = wm * 64 + mi * 16 + (lane & 15);
                    uint32_t off = swz64(row * 64 + cb);
                    ldm_x4(af[mi][0], af[mi][1], af[mi][2], af[mi][3], st + OFF_SA + off);
                }
                uint32_t b1f[4][2], b2f[4][2];
#pragma unroll
                for (int ni = 0; ni < 2; ni++) {
                    uint32_t row = wn * 32 + ni * 16 + (lane & 15);
                    uint32_t off = swz64(row * 64 + cb);
                    uint32_t r0, r1, r2, r3;
                    ldm_x4(r0, r1, r2, r3, st + OFF_SB1 + off);
                    b1f[2*ni][0] = r0; b1f[2*ni][1] = r2;
                    b1f[2*ni+1][0] = r1; b1f[2*ni+1][1] = r3;
                    ldm_x4(r0, r1, r2, r3, st + OFF_SB2 + off);
                    b2f[2*ni][0] = r0; b2f[2*ni][1] = r2;
                    b2f[2*ni+1][0] = r1; b2f[2*ni+1][1] = r3;
                }
#pragma unroll
                for (int mi = 0; mi < 4; mi++)
#pragma unroll
                    for (int nf = 0; nf < 4; nf++)
                        mma_f16(acc[mi][nf], af[mi], b1f[nf][0], b1f[nf][1]);
#pragma unroll
                for (int mi = 0; mi < 4; mi++)
#pragma unroll
                    for (int nf = 0; nf < 4; nf++)
                        mma_f16(acc[mi][nf], af[mi], b2f[nf][0], b2f[nf][1]);
            }
            __syncthreads();
        }

        // all cp.async drained before scanbuf overlays stage memory
        cp_wait<0>();
        __syncthreads();

        // dump accumulators: scanbuf[t_local][h_local]
        {
            const int group = lane >> 2, tid4 = lane & 3;
#pragma unroll
            for (int nf = 0; nf < 4; nf++) {
                int hc = wn * 32 + nf * 8 + tid4 * 2;
#pragma unroll
                for (int mi = 0; mi < 4; mi++) {
                    int tr = wm * 64 + mi * 16 + group;
                    float2 v0 = { acc[mi][nf][0], acc[mi][nf][1] };
                    float2 v1 = { acc[mi][nf][2], acc[mi][nf][3] };
                    *(float2*)&scanbuf[tr * SCAN_STRIDE + hc] = v0;
                    *(float2*)&scanbuf[(tr + 8) * SCAN_STRIDE + hc] = v1;
                }
            }
        }
        __syncthreads();

        // scan this chunk: threads 0..127, one h-col each
        if (tid < 128) {
#pragma unroll 1
            for (int t0 = 0; t0 < 128; t0 += 8) {
                float v[8];
#pragma unroll
                for (int j = 0; j < 8; j++)
                    v[j] = scanbuf[(t0 + j) * SCAN_STRIDE + tid];
#pragma unroll
                for (int j = 0; j < 8; j++) {
                    float y = v[j] + bb;
                    s_state = fmaxf(fmaf(uu, s_state, y), 0.f);
                    if (WRITE_NEXT) {
                        size_t m = (size_t)((tc * 128 + t0 + j) * BB + b);
                        Anext[m * HH + n0 + tid] = __float2half_rn(s_state);
                    }
                    l_sum += s_state;
                    l_sq = fmaf(s_state, s_state, l_sq);
                }
            }
        }
        __syncthreads();
    }

    if (tid < 128) {
        if (!WRITE_NEXT) hlast[(size_t)b * HH + n0 + tid] = s_state;
        atomicAdd(&gsum[n0 + tid], l_sum);
        atomicAdd(&gsumsq[n0 + tid], l_sq);
    }
}

__global__ void final_kernel(const float* __restrict__ hl,
                             const float* __restrict__ Wout,
                             const float* __restrict__ bout,
                             float* __restrict__ out) {
    __shared__ float sh[HH];
    int b = blockIdx.x;
    for (int h = threadIdx.x; h < HH; h += blockDim.x)
        sh[h] = fmaf(hl[b * HH + h], g_scale[h], g_shift[h]);
    __syncthreads();
    int c = threadIdx.x;
    if (c < CC) {
        float acc = bout[c];
#pragma unroll 8
        for (int h = 0; h < HH; h++)
            acc = fmaf(sh[h], Wout[c * HH + h], acc);
        out[b * CC + c] = acc;
    }
}

extern "C" void kernel_launch(void* const* d_in, const int* in_sizes, int n_in,
                              void* d_out, int out_size) {
    const float* x     = (const float*)d_in[0];
    const float* W0    = (const float*)d_in[1];
    const float* b0    = (const float*)d_in[2];
    const float* Wh    = (const float*)d_in[3];
    const float* bh    = (const float*)d_in[4];
    const float* u     = (const float*)d_in[5];
    const float* gamma = (const float*)d_in[6];
    const float* beta  = (const float*)d_in[7];
    const float* Wout  = (const float*)d_in[8];
    const float* bout  = (const float*)d_in[9];
    float* out = (float*)d_out;

    float *beff, *sum, *sumsq, *hlast;
    __half *Aping, *Apong, *B1, *B2;
    cudaGetSymbolAddress((void**)&Aping, g_Aping);
    cudaGetSymbolAddress((void**)&Apong, g_Apong);
    cudaGetSymbolAddress((void**)&B1, g_B1);
    cudaGetSymbolAddress((void**)&B2, g_B2);
    cudaGetSymbolAddress((void**)&beff, g_beff);
    cudaGetSymbolAddress((void**)&sum, g_sum);
    cudaGetSymbolAddress((void**)&sumsq, g_sumsq);
    cudaGetSymbolAddress((void**)&hlast, g_hlast);

    cudaFuncSetAttribute(layer_fused<true>, cudaFuncAttributeMaxDynamicSharedMemorySize, FSMEM);
    cudaFuncSetAttribute(layer_fused<false>, cudaFuncAttributeMaxDynamicSharedMemorySize, FSMEM);

    zero_stats_kernel<<<(LL * HH + 255) / 256, 256>>>();
    pad_x_kernel<<<(MM * K0P + 255) / 256, 256>>>(x);
    prep_w0_kernel<<<(HH * K0P + 255) / 256, 256>>>(W0, b0);

    dim3 fgrid(NN / BN, BB);

    // layer 0
    layer_fused<true><<<fgrid, GT, FSMEM>>>(Aping, B1, B2, beff, u, Apong,
                                            nullptr, sum, sumsq, K0P);
    __half* cur = Apong;
    __half* nxt = Aping;

    for (int l = 1; l < LL; l++) {
        const float* Wl  = Wh + (size_t)(l - 1) * HH * HH;
        const float* bhl = bh + (size_t)(l - 1) * HH;
        fold_all_kernel<<<HH, HH>>>(Wl, bhl, sum + (l - 1) * HH, sumsq + (l - 1) * HH,
                                    gamma + (l - 1) * HH, beta + (l - 1) * HH);
        if (l < LL - 1) {
            layer_fused<true><<<fgrid, GT, FSMEM>>>(cur, B1, B2, beff, u + l * HH, nxt,
                                                    nullptr, sum + l * HH, sumsq + l * HH, HH);
            __half* t = cur; cur = nxt; nxt = t;
        } else {
            layer_fused<false><<<fgrid, GT, FSMEM>>>(cur, B1, B2, beff, u + l * HH, nullptr,
                                                     hlast, sum + l * HH, sumsq + l * HH, HH);
        }
    }

    scale_shift_kernel<<<2, 256>>>(sum + (LL - 1) * HH, sumsq + (LL - 1) * HH,
                                   gamma + (LL - 1) * HH, beta + (LL - 1) * HH);
    final_kernel<<<BB, 64>>>(hlast, Wout, bout, out);
}